// round 6
// baseline (speedup 1.0000x reference)
#include <cuda_runtime.h>
#include <cuda_bf16.h>
#include <cstdint>

// Problem constants
#define SEQ    4096
#define DMODEL 1024
#define D3     3072
#define NHEAD  16
#define HDIM   64
#define WIN    512
#define NCHUNK 8

// Scratch (device globals: allocation-free per harness rules)
__device__ float    g_qkv[SEQ * D3];              // 48 MB
__device__ float    g_attn[SEQ * DMODEL];         // 16 MB
__device__ uint32_t g_xh[SEQ * DMODEL];           // x split planes
__device__ uint32_t g_xl[SEQ * DMODEL];
__device__ uint32_t g_wqh[D3 * DMODEL];           // w_qkv^T planes [N][K]
__device__ uint32_t g_wql[D3 * DMODEL];
__device__ uint32_t g_ath[SEQ * DMODEL];          // attn split planes
__device__ uint32_t g_atl[SEQ * DMODEL];
__device__ uint32_t g_woh[DMODEL * DMODEL];       // w_out^T planes [N][K]
__device__ uint32_t g_wol[DMODEL * DMODEL];

// ---------------------------------------------------------------------------
// tf32 helpers
// ---------------------------------------------------------------------------
__device__ __forceinline__ uint32_t f2tf32(float x) {
    uint32_t r;
    asm("cvt.rna.tf32.f32 %0, %1;" : "=r"(r) : "f"(x));
    return r;
}
__device__ __forceinline__ void split_tf32(float x, uint32_t& hi, uint32_t& lo) {
    hi = f2tf32(x);
    float l = x - __uint_as_float(hi);   // exact (Dekker split)
    lo = f2tf32(l);
}

#define MMA_TF32(d, a0, a1, a2, a3, b0, b1)                                    \
    asm volatile(                                                              \
        "mma.sync.aligned.m16n8k8.row.col.f32.tf32.tf32.f32 "                  \
        "{%0,%1,%2,%3}, {%4,%5,%6,%7}, {%8,%9}, {%0,%1,%2,%3};"                \
        : "+f"((d)[0]), "+f"((d)[1]), "+f"((d)[2]), "+f"((d)[3])               \
        : "r"(a0), "r"(a1), "r"(a2), "r"(a3), "r"(b0), "r"(b1))

#define LDSM_X4(r0, r1, r2, r3, addr)                                          \
    asm volatile("ldmatrix.sync.aligned.m8n8.x4.shared.b16 {%0,%1,%2,%3}, [%4];" \
        : "=r"(r0), "=r"(r1), "=r"(r2), "=r"(r3) : "r"(addr))

// ---------------------------------------------------------------------------
// Split kernels (run once per operand, outside the GEMM hot loop)
// ---------------------------------------------------------------------------
__global__ __launch_bounds__(256) void split2(const float* __restrict__ in,
                                              uint32_t* __restrict__ hp,
                                              uint32_t* __restrict__ lp, int n) {
    const int idx = (blockIdx.x * 256 + threadIdx.x) * 4;
    if (idx >= n) return;
    const float4 v = *(const float4*)(in + idx);
    uint4 h, l;
    split_tf32(v.x, h.x, l.x); split_tf32(v.y, h.y, l.y);
    split_tf32(v.z, h.z, l.z); split_tf32(v.w, h.w, l.w);
    *(uint4*)(hp + idx) = h;
    *(uint4*)(lp + idx) = l;
}

// transpose + split: w[Kd][Nd] fp32 -> planes [Nd][Kd]
__global__ void split2_t(const float* __restrict__ w,
                         uint32_t* __restrict__ th, uint32_t* __restrict__ tl,
                         int Kd, int Nd) {
    __shared__ float tile[32][33];
    const int k0 = blockIdx.y * 32, n0 = blockIdx.x * 32;
    const int tx = threadIdx.x, ty = threadIdx.y;
    for (int r = ty; r < 32; r += 8)
        tile[r][tx] = w[(size_t)(k0 + r) * Nd + n0 + tx];
    __syncthreads();
    for (int r = ty; r < 32; r += 8) {
        uint32_t h, l;
        split_tf32(tile[tx][r], h, l);
        const size_t o = (size_t)(n0 + r) * Kd + k0 + tx;
        th[o] = h; tl[o] = l;
    }
}

// ---------------------------------------------------------------------------
// 3xTF32 GEMM on pre-split planes. C[M,N] = A[M,K] x B[K,N].
// A given as hi/lo planes [M][K]; B given as hi/lo TRANSPOSED planes [N][K].
// 128x128 CTA tile, BK=32, 256 threads (8 warps 2m x 4n), 2 CTAs/SM.
// All fragments (A and B) loaded via conflict-free swizzled ldmatrix.x4.
// smem: 4 planes x 128 rows x 32 u32 = 64 KB.
// ---------------------------------------------------------------------------
__global__ __launch_bounds__(256, 2) void gemm_tf32p(
    const uint32_t* __restrict__ Ahg, const uint32_t* __restrict__ Alg,
    const uint32_t* __restrict__ Bhg, const uint32_t* __restrict__ Blg,
    float* __restrict__ C, int M, int N, int K) {
    extern __shared__ uint32_t sm[];

    const int tid  = threadIdx.x;
    const int lane = tid & 31;
    const int warp = tid >> 5;
    const int warp_m = warp >> 2;        // 0..1
    const int warp_n = warp & 3;         // 0..3

    const int m0 = blockIdx.y * 128;
    const int n0 = blockIdx.x * 128;

    // loader indices: 16 uint4 per thread per iter (4 planes x 1024 uint4)
    const int l_row = (tid & 1023) >> 3;   // reused per i via lin
    (void)l_row;

    // A-fragment ldmatrix lane mapping (16x8 tf32 = 4 b16 8x8 matrices)
    const int lm_row  = (lane & 7) + ((lane >> 3) & 1) * 8;  // 0..15
    const int lm_csel = lane >> 4;                            // 0/1

    // B-fragment ldmatrix lane mapping (2 n-frags x 2 k-chunks per x4)
    const int b_mat    = lane >> 3;        // matrix index 0..3
    const int b_nf_off = b_mat >> 1;       // 0,0,1,1
    const int b_kc     = b_mat & 1;        // 0,1,0,1
    const int b_row    = lane & 7;

    float acc[4][4][4] = {};

    const uint32_t sm_base = (uint32_t)__cvta_generic_to_shared(sm);
    const uint32_t ah_base = sm_base;
    const uint32_t al_base = sm_base + 16384;
    const uint32_t bh_base = sm_base + 32768;
    const uint32_t bl_base = sm_base + 49152;

    for (int k0 = 0; k0 < K; k0 += 32) {
        if (k0) __syncthreads();

        // ---- loader: pure LDG.128 -> swizzled STS.128, no conversion ----
        #pragma unroll
        for (int i = 0; i < 16; i++) {
            const int lin = tid + i * 256;     // 0..4095
            const int pl  = lin >> 10;         // 0:Ah 1:Al 2:Bh 3:Bl
            const int rem = lin & 1023;
            const int row = rem >> 3;
            const int ch  = rem & 7;
            const uint32_t* src;
            if      (pl == 0) src = Ahg + (size_t)(m0 + row) * K;
            else if (pl == 1) src = Alg + (size_t)(m0 + row) * K;
            else if (pl == 2) src = Bhg + (size_t)(n0 + row) * K;
            else              src = Blg + (size_t)(n0 + row) * K;
            const uint4 v = *(const uint4*)(src + k0 + ch * 4);
            *(uint4*)&sm[pl * 4096 + row * 32 + ((ch ^ (row & 7)) << 2)] = v;
        }
        __syncthreads();

        // ---- compute: 4 k8-steps ----
        #pragma unroll
        for (int k8 = 0; k8 < 4; k8++) {
            // A fragments (hi & lo), 4 m-frags
            uint32_t aH[4][4], aL[4][4];
            #pragma unroll
            for (int mf = 0; mf < 4; mf++) {
                const int m = warp_m * 64 + mf * 16 + lm_row;
                const uint32_t foff =
                    4u * (m * 32 + (((2 * k8 + lm_csel) ^ (m & 7)) << 2));
                LDSM_X4(aH[mf][0], aH[mf][1], aH[mf][2], aH[mf][3], ah_base + foff);
                LDSM_X4(aL[mf][0], aL[mf][1], aL[mf][2], aL[mf][3], al_base + foff);
            }
            // B fragments (hi & lo), 4 n-frags via 2 ldmatrix.x4 per plane
            uint32_t bH[2][4], bL[2][4];
            #pragma unroll
            for (int p = 0; p < 2; p++) {
                const int n = warp_n * 32 + (2 * p + b_nf_off) * 8 + b_row;
                const uint32_t foff =
                    4u * (n * 32 + (((2 * k8 + b_kc) ^ (n & 7)) << 2));
                LDSM_X4(bH[p][0], bH[p][1], bH[p][2], bH[p][3], bh_base + foff);
                LDSM_X4(bL[p][0], bL[p][1], bL[p][2], bL[p][3], bl_base + foff);
            }
            // MMAs: 4mf x 4nf x 3 products
            #pragma unroll
            for (int p = 0; p < 2; p++)
                #pragma unroll
                for (int sub = 0; sub < 2; sub++) {
                    const int nf = 2 * p + sub;
                    const uint32_t bh0 = bH[p][2 * sub], bh1 = bH[p][2 * sub + 1];
                    const uint32_t bl0 = bL[p][2 * sub], bl1 = bL[p][2 * sub + 1];
                    #pragma unroll
                    for (int mf = 0; mf < 4; mf++) {
                        MMA_TF32(acc[mf][nf], aH[mf][0], aH[mf][1], aH[mf][2], aH[mf][3], bh0, bh1);
                        MMA_TF32(acc[mf][nf], aH[mf][0], aH[mf][1], aH[mf][2], aH[mf][3], bl0, bl1);
                        MMA_TF32(acc[mf][nf], aL[mf][0], aL[mf][1], aL[mf][2], aL[mf][3], bh0, bh1);
                    }
                }
        }
    }

    // ---- epilogue ----
    const int row_in = lane >> 2;
    const int col_in = 2 * (lane & 3);
    #pragma unroll
    for (int mf = 0; mf < 4; mf++) {
        const int gr = m0 + warp_m * 64 + mf * 16 + row_in;
        #pragma unroll
        for (int nf = 0; nf < 4; nf++) {
            const int gc = n0 + warp_n * 32 + nf * 8 + col_in;
            *(float2*)(C + (size_t)gr * N + gc) =
                make_float2(acc[mf][nf][0], acc[mf][nf][1]);
            *(float2*)(C + (size_t)(gr + 8) * N + gc) =
                make_float2(acc[mf][nf][2], acc[mf][nf][3]);
        }
    }
}

// ---------------------------------------------------------------------------
// Sliding-window attention with 3xTF32 tensor-core MMAs (unchanged from R5).
// ---------------------------------------------------------------------------
struct AttnSmem2 {
    float Qh[64][68];
    float Ql[64][68];
    float Ks[64][68];
    float Vs[64][68];
    float Ps[64][68];
    float Pl[64][68];
    float m_s[64], l_s[64], alpha_s[64];
};

__global__ __launch_bounds__(256, 2) void attn_mma(const float* __restrict__ qkv,
                                                   float* __restrict__ out) {
    extern __shared__ char smem_raw[];
    AttnSmem2& sm = *reinterpret_cast<AttnSmem2*>(smem_raw);

    const int qt = blockIdx.x;
    const int c  = blockIdx.y;
    const int h  = blockIdx.z;
    const int tid  = threadIdx.x;
    const int lane = tid & 31;
    const int warp = tid >> 5;
    const int warp_m = warp >> 2;
    const int warp_n = warp & 3;

    const int q0 = qt * 64;
    const int qrow0 = c * WIN + q0;

    const int lm_row  = (lane & 7) + ((lane >> 3) & 1) * 8;
    const int lm_csel = lane >> 4;
    const int bf_n = lane >> 2;
    const int bf_k = lane & 3;

    const uint32_t qh_base = (uint32_t)__cvta_generic_to_shared(&sm.Qh[0][0]);
    const uint32_t ql_base = (uint32_t)__cvta_generic_to_shared(&sm.Ql[0][0]);
    const uint32_t ps_base = (uint32_t)__cvta_generic_to_shared(&sm.Ps[0][0]);
    const uint32_t pl_base = (uint32_t)__cvta_generic_to_shared(&sm.Pl[0][0]);

    {
        const int q = tid >> 2;
        const float* src = qkv + (size_t)(qrow0 + q) * D3 + h * HDIM;
        #pragma unroll
        for (int i = 0; i < 4; i++) {
            const int cd = (tid & 3) + i * 4;
            const float4 v = *(const float4*)(src + cd * 4);
            uint4 hh, ll;
            split_tf32(v.x, hh.x, ll.x); split_tf32(v.y, hh.y, ll.y);
            split_tf32(v.z, hh.z, ll.z); split_tf32(v.w, hh.w, ll.w);
            *(uint4*)&sm.Qh[q][cd * 4] = hh;
            *(uint4*)&sm.Ql[q][cd * 4] = ll;
        }
    }
    if (tid < 64) { sm.m_s[tid] = -1e30f; sm.l_s[tid] = 0.f; }

    float o[2][2][4] = {};
    const int kb_start = (c == 0) ? (WIN / 64) : 0;
    const int kb_end = ((q0 + 63 + WIN) >> 6) + 1;

    for (int kb = kb_start; kb < kb_end; kb++) {
        const int j0 = kb * 64;
        __syncthreads();

        {
            const int j = tid >> 2;
            const int krow = c * WIN + j0 - WIN + j;
            const float* ksrc = qkv + (size_t)krow * D3 + DMODEL + h * HDIM;
            const float* vsrc = qkv + (size_t)krow * D3 + 2 * DMODEL + h * HDIM;
            #pragma unroll
            for (int i = 0; i < 4; i++) {
                const int cd = (tid & 3) + i * 4;
                const float4 kv = *(const float4*)(ksrc + cd * 4);
                sm.Ks[cd*4+0][j] = kv.x; sm.Ks[cd*4+1][j] = kv.y;
                sm.Ks[cd*4+2][j] = kv.z; sm.Ks[cd*4+3][j] = kv.w;
                const float4 vv = *(const float4*)(vsrc + cd * 4);
                *(float4*)&sm.Vs[j][cd * 4] = vv;
            }
        }
        __syncthreads();

        float s[2][2][4] = {};
        #pragma unroll
        for (int k8 = 0; k8 < 8; k8++) {
            uint32_t aH[2][4], aL[2][4];
            #pragma unroll
            for (int mf = 0; mf < 2; mf++) {
                const int qrow = warp_m * 32 + mf * 16 + lm_row;
                const uint32_t foff = 4u * (qrow * 68 + (k8 * 2 + lm_csel) * 4);
                LDSM_X4(aH[mf][0], aH[mf][1], aH[mf][2], aH[mf][3], qh_base + foff);
                LDSM_X4(aL[mf][0], aL[mf][1], aL[mf][2], aL[mf][3], ql_base + foff);
            }
            const int kk = k8 * 8;
            #pragma unroll
            for (int nf = 0; nf < 2; nf++) {
                const int j = warp_n * 16 + nf * 8 + bf_n;
                uint32_t bh0, bl0, bh1, bl1;
                split_tf32(sm.Ks[kk + bf_k][j], bh0, bl0);
                split_tf32(sm.Ks[kk + 4 + bf_k][j], bh1, bl1);
                #pragma unroll
                for (int mf = 0; mf < 2; mf++) {
                    MMA_TF32(s[mf][nf], aH[mf][0], aH[mf][1], aH[mf][2], aH[mf][3], bh0, bh1);
                    MMA_TF32(s[mf][nf], aH[mf][0], aH[mf][1], aH[mf][2], aH[mf][3], bl0, bl1);
                    MMA_TF32(s[mf][nf], aL[mf][0], aL[mf][1], aL[mf][2], aL[mf][3], bh0, bh1);
                }
            }
        }

        #pragma unroll
        for (int mf = 0; mf < 2; mf++) {
            const int r0 = warp_m * 32 + mf * 16 + (lane >> 2);
            #pragma unroll
            for (int nf = 0; nf < 2; nf++) {
                const int cb = warp_n * 16 + nf * 8 + 2 * (lane & 3);
                const int jg0 = j0 + cb;
                const float sc = 0.125f;
                sm.Ps[r0][cb]       = (q0 + r0 + WIN >= jg0)     ? s[mf][nf][0] * sc : -1e30f;
                sm.Ps[r0][cb + 1]   = (q0 + r0 + WIN >= jg0 + 1) ? s[mf][nf][1] * sc : -1e30f;
                sm.Ps[r0 + 8][cb]     = (q0 + r0 + 8 + WIN >= jg0)     ? s[mf][nf][2] * sc : -1e30f;
                sm.Ps[r0 + 8][cb + 1] = (q0 + r0 + 8 + WIN >= jg0 + 1) ? s[mf][nf][3] * sc : -1e30f;
            }
        }
        __syncthreads();

        {
            const int q = tid >> 2;
            const int r = tid & 3;
            float mx = -1e30f;
            #pragma unroll
            for (int t = 0; t < 16; t++) mx = fmaxf(mx, sm.Ps[q][r * 16 + t]);
            mx = fmaxf(mx, __shfl_xor_sync(0xffffffffu, mx, 1));
            mx = fmaxf(mx, __shfl_xor_sync(0xffffffffu, mx, 2));
            const float m_old = sm.m_s[q];
            const float m_new = fmaxf(m_old, mx);
            float sum = 0.f;
            #pragma unroll
            for (int t = 0; t < 16; t++) {
                const float p = __expf(sm.Ps[q][r * 16 + t] - m_new);
                sum += p;
                uint32_t ph, pl;
                split_tf32(p, ph, pl);
                sm.Ps[q][r * 16 + t] = __uint_as_float(ph);
                sm.Pl[q][r * 16 + t] = __uint_as_float(pl);
            }
            sum += __shfl_xor_sync(0xffffffffu, sum, 1);
            sum += __shfl_xor_sync(0xffffffffu, sum, 2);
            if (r == 0) {
                const float alpha = __expf(m_old - m_new);
                sm.m_s[q] = m_new;
                sm.l_s[q] = sm.l_s[q] * alpha + sum;
                sm.alpha_s[q] = alpha;
            }
        }
        __syncthreads();

        #pragma unroll
        for (int mf = 0; mf < 2; mf++) {
            const int r0 = warp_m * 32 + mf * 16 + (lane >> 2);
            const float a0 = sm.alpha_s[r0];
            const float a1 = sm.alpha_s[r0 + 8];
            #pragma unroll
            for (int nf = 0; nf < 2; nf++) {
                o[mf][nf][0] *= a0; o[mf][nf][1] *= a0;
                o[mf][nf][2] *= a1; o[mf][nf][3] *= a1;
            }
        }
        #pragma unroll
        for (int k8 = 0; k8 < 8; k8++) {
            uint32_t aH[2][4], aL[2][4];
            #pragma unroll
            for (int mf = 0; mf < 2; mf++) {
                const int qrow = warp_m * 32 + mf * 16 + lm_row;
                const uint32_t foff = 4u * (qrow * 68 + (k8 * 2 + lm_csel) * 4);
                LDSM_X4(aH[mf][0], aH[mf][1], aH[mf][2], aH[mf][3], ps_base + foff);
                LDSM_X4(aL[mf][0], aL[mf][1], aL[mf][2], aL[mf][3], pl_base + foff);
            }
            const int kk = k8 * 8;
            #pragma unroll
            for (int nf = 0; nf < 2; nf++) {
                const int d = warp_n * 16 + nf * 8 + bf_n;
                uint32_t bh0, bl0, bh1, bl1;
                split_tf32(sm.Vs[kk + bf_k][d], bh0, bl0);
                split_tf32(sm.Vs[kk + 4 + bf_k][d], bh1, bl1);
                #pragma unroll
                for (int mf = 0; mf < 2; mf++) {
                    MMA_TF32(o[mf][nf], aH[mf][0], aH[mf][1], aH[mf][2], aH[mf][3], bh0, bh1);
                    MMA_TF32(o[mf][nf], aH[mf][0], aH[mf][1], aH[mf][2], aH[mf][3], bl0, bl1);
                    MMA_TF32(o[mf][nf], aL[mf][0], aL[mf][1], aL[mf][2], aL[mf][3], bh0, bh1);
                }
            }
        }
    }

    #pragma unroll
    for (int mf = 0; mf < 2; mf++) {
        const int r0 = warp_m * 32 + mf * 16 + (lane >> 2);
        const float inv0 = 1.f / sm.l_s[r0];
        const float inv1 = 1.f / sm.l_s[r0 + 8];
        #pragma unroll
        for (int nf = 0; nf < 2; nf++) {
            const int col = h * HDIM + warp_n * 16 + nf * 8 + 2 * (lane & 3);
            *(float2*)(out + (size_t)(qrow0 + r0) * DMODEL + col) =
                make_float2(o[mf][nf][0] * inv0, o[mf][nf][1] * inv0);
            *(float2*)(out + (size_t)(qrow0 + r0 + 8) * DMODEL + col) =
                make_float2(o[mf][nf][2] * inv1, o[mf][nf][3] * inv1);
        }
    }
}

// ---------------------------------------------------------------------------
extern "C" void kernel_launch(void* const* d_in, const int* in_sizes, int n_in,
                              void* d_out, int out_size) {
    const float* x      = (const float*)d_in[0];   // [4096,1024]
    const float* w_qkv  = (const float*)d_in[1];   // [1024,3072]
    const float* w_out  = (const float*)d_in[2];   // [1024,1024]
    float* out = (float*)d_out;                    // [4096,1024]

    float *qkv, *attn;
    uint32_t *xh, *xl, *wqh, *wql, *ath, *atl, *woh, *wol;
    cudaGetSymbolAddress((void**)&qkv, g_qkv);
    cudaGetSymbolAddress((void**)&attn, g_attn);
    cudaGetSymbolAddress((void**)&xh, g_xh);
    cudaGetSymbolAddress((void**)&xl, g_xl);
    cudaGetSymbolAddress((void**)&wqh, g_wqh);
    cudaGetSymbolAddress((void**)&wql, g_wql);
    cudaGetSymbolAddress((void**)&ath, g_ath);
    cudaGetSymbolAddress((void**)&atl, g_atl);
    cudaGetSymbolAddress((void**)&woh, g_woh);
    cudaGetSymbolAddress((void**)&wol, g_wol);

    const int gemm_smem = 65536;
    cudaFuncSetAttribute(gemm_tf32p, cudaFuncAttributeMaxDynamicSharedMemorySize,
                         gemm_smem);
    cudaFuncSetAttribute(attn_mma, cudaFuncAttributeMaxDynamicSharedMemorySize,
                         (int)sizeof(AttnSmem2));

    const int NX = SEQ * DMODEL;   // 4M elements

    // split x and w_qkv
    split2<<<NX / 4 / 256, 256>>>(x, xh, xl, NX);
    split2_t<<<dim3(D3 / 32, DMODEL / 32), dim3(32, 8)>>>(w_qkv, wqh, wql,
                                                          DMODEL, D3);
    // 1) qkv = x @ w_qkv
    gemm_tf32p<<<dim3(D3 / 128, SEQ / 128), 256, gemm_smem>>>(
        xh, xl, wqh, wql, qkv, SEQ, D3, DMODEL);

    // 2) sliding-window attention
    attn_mma<<<dim3(8, NCHUNK, NHEAD), 256, sizeof(AttnSmem2)>>>(qkv, attn);

    // split attn and w_out
    split2<<<NX / 4 / 256, 256>>>(attn, ath, atl, NX);
    split2_t<<<dim3(DMODEL / 32, DMODEL / 32), dim3(32, 8)>>>(w_out, woh, wol,
                                                              DMODEL, DMODEL);
    // 3) out = attn @ w_out
    gemm_tf32p<<<dim3(DMODEL / 128, SEQ / 128), 256, gemm_smem>>>(
        ath, atl, woh, wol, out, SEQ, DMODEL, DMODEL);
}

// round 7
// speedup vs baseline: 1.6822x; 1.6822x over previous
#include <cuda_runtime.h>
#include <cuda_fp16.h>
#include <cstdint>

// Problem constants
#define SEQ    4096
#define DMODEL 1024
#define D3     3072
#define NHEAD  16
#define HDIM   64
#define WIN    512
#define NCHUNK 8

// Scratch (device globals: allocation-free per harness rules)
__device__ float  g_qkv[SEQ * D3];            // 48 MB
__device__ float  g_attn[SEQ * DMODEL];       // 16 MB
__device__ __half g_xh[SEQ * DMODEL];         // x split planes (scaled 256)
__device__ __half g_xl[SEQ * DMODEL];
__device__ __half g_wqh[D3 * DMODEL];         // w_qkv^T planes [N][K] (scaled 256)
__device__ __half g_wql[D3 * DMODEL];
__device__ __half g_ath[SEQ * DMODEL];        // attn split planes
__device__ __half g_atl[SEQ * DMODEL];
__device__ __half g_woh[DMODEL * DMODEL];     // w_out^T planes [N][K]
__device__ __half g_wol[DMODEL * DMODEL];

// ---------------------------------------------------------------------------
// helpers
// ---------------------------------------------------------------------------
__device__ __forceinline__ void split_h(float x, __half& hi, __half& lo) {
    hi = __float2half_rn(x);
    lo = __float2half_rn(x - __half2float(hi));
}
__device__ __forceinline__ uint32_t pack_h2(__half a, __half b) {
    __half2 h = __halves2half2(a, b);
    return *reinterpret_cast<uint32_t*>(&h);
}

#define MMA_F16(d, a0, a1, a2, a3, b0, b1)                                     \
    asm volatile(                                                              \
        "mma.sync.aligned.m16n8k16.row.col.f32.f16.f16.f32 "                   \
        "{%0,%1,%2,%3}, {%4,%5,%6,%7}, {%8,%9}, {%0,%1,%2,%3};"                \
        : "+f"((d)[0]), "+f"((d)[1]), "+f"((d)[2]), "+f"((d)[3])               \
        : "r"(a0), "r"(a1), "r"(a2), "r"(a3), "r"(b0), "r"(b1))

#define LDSM_X4(r0, r1, r2, r3, addr)                                          \
    asm volatile("ldmatrix.sync.aligned.m8n8.x4.shared.b16 {%0,%1,%2,%3}, [%4];" \
        : "=r"(r0), "=r"(r1), "=r"(r2), "=r"(r3) : "r"(addr))

// ---------------------------------------------------------------------------
// Split kernels (scale by 256 exactly, then Dekker split to fp16 hi/lo)
// ---------------------------------------------------------------------------
__global__ __launch_bounds__(256) void split2h(const float* __restrict__ in,
                                               __half* __restrict__ hp,
                                               __half* __restrict__ lp, int n) {
    const int idx = (blockIdx.x * 256 + threadIdx.x) * 4;
    if (idx >= n) return;
    const float4 v = *(const float4*)(in + idx);
    __half hx, lx, hy, ly, hz, lz, hw, lw;
    split_h(v.x * 256.f, hx, lx); split_h(v.y * 256.f, hy, ly);
    split_h(v.z * 256.f, hz, lz); split_h(v.w * 256.f, hw, lw);
    uint2 hh = make_uint2(pack_h2(hx, hy), pack_h2(hz, hw));
    uint2 ll = make_uint2(pack_h2(lx, ly), pack_h2(lz, lw));
    *(uint2*)(hp + idx) = hh;
    *(uint2*)(lp + idx) = ll;
}

// transpose + split: w[Kd][Nd] fp32 -> planes [Nd][Kd] fp16 (scaled 256)
__global__ void split2h_t(const float* __restrict__ w,
                          __half* __restrict__ th, __half* __restrict__ tl,
                          int Kd, int Nd) {
    __shared__ float tile[32][33];
    const int k0 = blockIdx.y * 32, n0 = blockIdx.x * 32;
    const int tx = threadIdx.x, ty = threadIdx.y;
    for (int r = ty; r < 32; r += 8)
        tile[r][tx] = w[(size_t)(k0 + r) * Nd + n0 + tx];
    __syncthreads();
    for (int r = ty; r < 32; r += 8) {
        __half h, l;
        split_h(tile[tx][r] * 256.f, h, l);
        const size_t o = (size_t)(n0 + r) * Kd + k0 + tx;
        th[o] = h; tl[o] = l;
    }
}

// ---------------------------------------------------------------------------
// 3xFP16 GEMM (m16n8k16). C[M,N] = (A x B) * outscale.
// A hi/lo fp16 planes [M][K]; B hi/lo fp16 planes TRANSPOSED [N][K].
// 128x128 CTA tile, BK=64, 256 threads (8 warps 2m x 4n), 2 CTAs/SM.
// smem: 4 planes x 128 rows x 128 B (swizzled 16B chunks) = 64 KB.
// ---------------------------------------------------------------------------
__global__ __launch_bounds__(256, 2) void gemm_f16x3(
    const __half* __restrict__ Ahg, const __half* __restrict__ Alg,
    const __half* __restrict__ Bhg, const __half* __restrict__ Blg,
    float* __restrict__ C, int M, int N, int K, float outscale) {
    extern __shared__ char smc[];

    const int tid  = threadIdx.x;
    const int lane = tid & 31;
    const int warp = tid >> 5;
    const int warp_m = warp >> 2;        // 0..1
    const int warp_n = warp & 3;         // 0..3

    const int m0 = blockIdx.y * 128;
    const int n0 = blockIdx.x * 128;

    const int lm_row  = (lane & 7) + ((lane >> 3) & 1) * 8;  // 0..15
    const int lm_csel = lane >> 4;                            // 0/1
    const int bq = lane >> 2;            // 0..7 (n within frag)
    const int bi = lane & 3;             // 0..3 (k-pair)

    float acc[4][4][4] = {};

    const uint32_t sm_base = (uint32_t)__cvta_generic_to_shared(smc);
    const uint32_t ah_base = sm_base;
    const uint32_t al_base = sm_base + 16384;
    const uint32_t* BH32 = (const uint32_t*)(smc + 32768);
    const uint32_t* BL32 = (const uint32_t*)(smc + 49152);

    for (int k0 = 0; k0 < K; k0 += 64) {
        if (k0) __syncthreads();

        // ---- loader: LDG.128 -> swizzled STS.128 (fp16, no conversion) ----
        #pragma unroll
        for (int i = 0; i < 16; i++) {
            const int lin = tid + i * 256;     // 0..4095
            const int pl  = lin >> 10;         // 0:Ah 1:Al 2:Bh 3:Bl
            const int rem = lin & 1023;
            const int row = rem >> 3;          // 0..127
            const int ch  = rem & 7;           // 16B chunk (8 fp16)
            const __half* src;
            if      (pl == 0) src = Ahg + (size_t)(m0 + row) * K;
            else if (pl == 1) src = Alg + (size_t)(m0 + row) * K;
            else if (pl == 2) src = Bhg + (size_t)(n0 + row) * K;
            else              src = Blg + (size_t)(n0 + row) * K;
            const uint4 v = *(const uint4*)(src + k0 + ch * 8);
            *(uint4*)(smc + pl * 16384 + row * 128 + ((ch ^ (row & 7)) << 4)) = v;
        }
        __syncthreads();

        // ---- compute: 4 k16-steps ----
        #pragma unroll
        for (int s = 0; s < 4; s++) {
            uint32_t aH[4][4], aL[4][4];
            #pragma unroll
            for (int mf = 0; mf < 4; mf++) {
                const int m = warp_m * 64 + mf * 16 + lm_row;
                const uint32_t off =
                    (uint32_t)(m * 128 + (((2 * s + lm_csel) ^ (m & 7)) << 4));
                LDSM_X4(aH[mf][0], aH[mf][1], aH[mf][2], aH[mf][3], ah_base + off);
                LDSM_X4(aL[mf][0], aL[mf][1], aL[mf][2], aL[mf][3], al_base + off);
            }
            #pragma unroll
            for (int nf = 0; nf < 4; nf++) {
                const int n = warp_n * 32 + nf * 8 + bq;
                const int i0 = n * 32 + (((2 * s)     ^ (n & 7)) << 2) + bi;
                const int i1 = n * 32 + (((2 * s + 1) ^ (n & 7)) << 2) + bi;
                const uint32_t bh0 = BH32[i0], bh1 = BH32[i1];
                const uint32_t bl0 = BL32[i0], bl1 = BL32[i1];
                #pragma unroll
                for (int mf = 0; mf < 4; mf++) {
                    MMA_F16(acc[mf][nf], aH[mf][0], aH[mf][1], aH[mf][2], aH[mf][3], bh0, bh1);
                    MMA_F16(acc[mf][nf], aH[mf][0], aH[mf][1], aH[mf][2], aH[mf][3], bl0, bl1);
                    MMA_F16(acc[mf][nf], aL[mf][0], aL[mf][1], aL[mf][2], aL[mf][3], bh0, bh1);
                }
            }
        }
    }

    // ---- epilogue (scale back) ----
    const int row_in = lane >> 2;
    const int col_in = 2 * (lane & 3);
    #pragma unroll
    for (int mf = 0; mf < 4; mf++) {
        const int gr = m0 + warp_m * 64 + mf * 16 + row_in;
        #pragma unroll
        for (int nf = 0; nf < 4; nf++) {
            const int gc = n0 + warp_n * 32 + nf * 8 + col_in;
            *(float2*)(C + (size_t)gr * N + gc) =
                make_float2(acc[mf][nf][0] * outscale, acc[mf][nf][1] * outscale);
            *(float2*)(C + (size_t)(gr + 8) * N + gc) =
                make_float2(acc[mf][nf][2] * outscale, acc[mf][nf][3] * outscale);
        }
    }
}

// ---------------------------------------------------------------------------
// Sliding-window attention with 3xFP16 MMAs (m16n8k16).
// Q,K,V scaled by 256 and split to fp16 hi/lo at smem-store time;
// P scaled by 2048 and split at softmax time. Scales folded into finalize.
// smem byte layout (all fp16 planes are 64 rows x 128B, chunk-swizzled):
//   QH 0, QL 8192, KH 16384 ([j][d]), KL 24576, VTH 32768 ([d][j]), VTL 40960,
//   SS 49152 (f32 [64][68]), PH 66560, PL 74752, stats 82944..83712
// ---------------------------------------------------------------------------
#define AT_QH 0
#define AT_QL 8192
#define AT_KH 16384
#define AT_KL 24576
#define AT_VTH 32768
#define AT_VTL 40960
#define AT_SS 49152
#define AT_PH 66560
#define AT_PL 74752
#define AT_M  82944
#define AT_L  83200
#define AT_AL 83456
#define AT_SMEM 83712

__global__ __launch_bounds__(256, 2) void attn_f16(const float* __restrict__ qkv,
                                                   float* __restrict__ out) {
    extern __shared__ char smc[];
    float (*Ss)[68] = (float(*)[68])(smc + AT_SS);
    float* m_s = (float*)(smc + AT_M);
    float* l_s = (float*)(smc + AT_L);
    float* al_s = (float*)(smc + AT_AL);

    const int qt = blockIdx.x;
    const int c  = blockIdx.y;
    const int h  = blockIdx.z;
    const int tid  = threadIdx.x;
    const int lane = tid & 31;
    const int warp = tid >> 5;
    const int warp_m = warp >> 2;     // 0..1 (32 q rows each)
    const int warp_n = warp & 3;      // 0..3 (16 cols each)

    const int q0 = qt * 64;
    const int qrow0 = c * WIN + q0;

    const int lm_row  = (lane & 7) + ((lane >> 3) & 1) * 8;
    const int lm_csel = lane >> 4;
    const int bq = lane >> 2;
    const int bi = lane & 3;

    const uint32_t sm_base = (uint32_t)__cvta_generic_to_shared(smc);
    const uint32_t* KH32 = (const uint32_t*)(smc + AT_KH);
    const uint32_t* KL32 = (const uint32_t*)(smc + AT_KL);
    const uint32_t* VTH32 = (const uint32_t*)(smc + AT_VTH);
    const uint32_t* VTL32 = (const uint32_t*)(smc + AT_VTL);

    // ---- load Q tile, scale x256, split to QH/QL (row q, 64 fp16, swizzled) ----
    {
        const int q = tid >> 2;
        const float* src = qkv + (size_t)(qrow0 + q) * D3 + h * HDIM;
        #pragma unroll
        for (int i = 0; i < 4; i++) {
            const int cd = (tid & 3) + i * 4;            // float4 chunk 0..15
            const float4 v = *(const float4*)(src + cd * 4);
            __half hx, lx, hy, ly, hz, lz, hw, lw;
            split_h(v.x * 256.f, hx, lx); split_h(v.y * 256.f, hy, ly);
            split_h(v.z * 256.f, hz, lz); split_h(v.w * 256.f, hw, lw);
            const int byte = q * 128 + (((cd >> 1) ^ (q & 7)) << 4) + (cd & 1) * 8;
            *(uint2*)(smc + AT_QH + byte) = make_uint2(pack_h2(hx, hy), pack_h2(hz, hw));
            *(uint2*)(smc + AT_QL + byte) = make_uint2(pack_h2(lx, ly), pack_h2(lz, lw));
        }
    }
    if (tid < 64) { m_s[tid] = -1e30f; l_s[tid] = 0.f; }

    float o[2][2][4] = {};
    const int kb_start = (c == 0) ? (WIN / 64) : 0;
    const int kb_end = ((q0 + 63 + WIN) >> 6) + 1;   // exclusive, <= 16

    for (int kb = kb_start; kb < kb_end; kb++) {
        const int j0 = kb * 64;
        __syncthreads();

        // ---- load K -> KH/KL [j][d]; V -> VTH/VTL [d][j]; scale 256, split ----
        {
            const int j = tid >> 2;
            const int krow = c * WIN + j0 - WIN + j;
            const float* ksrc = qkv + (size_t)krow * D3 + DMODEL + h * HDIM;
            const float* vsrc = qkv + (size_t)krow * D3 + 2 * DMODEL + h * HDIM;
            #pragma unroll
            for (int i = 0; i < 4; i++) {
                const int cd = (tid & 3) + i * 4;
                const float4 kv = *(const float4*)(ksrc + cd * 4);
                __half hx, lx, hy, ly, hz, lz, hw, lw;
                split_h(kv.x * 256.f, hx, lx); split_h(kv.y * 256.f, hy, ly);
                split_h(kv.z * 256.f, hz, lz); split_h(kv.w * 256.f, hw, lw);
                const int byte = j * 128 + (((cd >> 1) ^ (j & 7)) << 4) + (cd & 1) * 8;
                *(uint2*)(smc + AT_KH + byte) = make_uint2(pack_h2(hx, hy), pack_h2(hz, hw));
                *(uint2*)(smc + AT_KL + byte) = make_uint2(pack_h2(lx, ly), pack_h2(lz, lw));

                const float4 vv = *(const float4*)(vsrc + cd * 4);
                const float vals[4] = {vv.x, vv.y, vv.z, vv.w};
                #pragma unroll
                for (int e = 0; e < 4; e++) {
                    const int d = cd * 4 + e;
                    __half hv, lv;
                    split_h(vals[e] * 256.f, hv, lv);
                    const int vb = d * 128 + (((j >> 3) ^ (d & 7)) << 4) + (j & 7) * 2;
                    *(__half*)(smc + AT_VTH + vb) = hv;
                    *(__half*)(smc + AT_VTL + vb) = lv;
                }
            }
        }
        __syncthreads();

        // ---- S = Q K^T (64x64x64), 3xfp16 k16 ----
        float s[2][2][4] = {};
        #pragma unroll
        for (int ks = 0; ks < 4; ks++) {
            uint32_t aH[2][4], aL[2][4];
            #pragma unroll
            for (int mf = 0; mf < 2; mf++) {
                const int q = warp_m * 32 + mf * 16 + lm_row;
                const uint32_t off =
                    (uint32_t)(q * 128 + (((2 * ks + lm_csel) ^ (q & 7)) << 4));
                LDSM_X4(aH[mf][0], aH[mf][1], aH[mf][2], aH[mf][3], sm_base + AT_QH + off);
                LDSM_X4(aL[mf][0], aL[mf][1], aL[mf][2], aL[mf][3], sm_base + AT_QL + off);
            }
            #pragma unroll
            for (int nf = 0; nf < 2; nf++) {
                const int j = warp_n * 16 + nf * 8 + bq;
                const int i0 = j * 32 + (((2 * ks)     ^ (j & 7)) << 2) + bi;
                const int i1 = j * 32 + (((2 * ks + 1) ^ (j & 7)) << 2) + bi;
                const uint32_t bh0 = KH32[i0], bh1 = KH32[i1];
                const uint32_t bl0 = KL32[i0], bl1 = KL32[i1];
                #pragma unroll
                for (int mf = 0; mf < 2; mf++) {
                    MMA_F16(s[mf][nf], aH[mf][0], aH[mf][1], aH[mf][2], aH[mf][3], bh0, bh1);
                    MMA_F16(s[mf][nf], aH[mf][0], aH[mf][1], aH[mf][2], aH[mf][3], bl0, bl1);
                    MMA_F16(s[mf][nf], aL[mf][0], aL[mf][1], aL[mf][2], aL[mf][3], bh0, bh1);
                }
            }
        }

        // ---- mask + scale (0.125 / 65536), write scores to Ss[q][j] ----
        const float sc = 0.125f / 65536.f;
        #pragma unroll
        for (int mf = 0; mf < 2; mf++) {
            const int r0 = warp_m * 32 + mf * 16 + (lane >> 2);
            #pragma unroll
            for (int nf = 0; nf < 2; nf++) {
                const int cb = warp_n * 16 + nf * 8 + 2 * (lane & 3);
                const int jg0 = j0 + cb;
                Ss[r0][cb]       = (q0 + r0 + WIN >= jg0)     ? s[mf][nf][0] * sc : -1e30f;
                Ss[r0][cb + 1]   = (q0 + r0 + WIN >= jg0 + 1) ? s[mf][nf][1] * sc : -1e30f;
                Ss[r0 + 8][cb]     = (q0 + r0 + 8 + WIN >= jg0)     ? s[mf][nf][2] * sc : -1e30f;
                Ss[r0 + 8][cb + 1] = (q0 + r0 + 8 + WIN >= jg0 + 1) ? s[mf][nf][3] * sc : -1e30f;
            }
        }
        __syncthreads();

        // ---- online softmax (4 threads/query); P = 2048*exp split to PH/PL ----
        {
            const int q = tid >> 2;
            const int r = tid & 3;
            float mx = -1e30f;
            #pragma unroll
            for (int t = 0; t < 16; t++) mx = fmaxf(mx, Ss[q][r * 16 + t]);
            mx = fmaxf(mx, __shfl_xor_sync(0xffffffffu, mx, 1));
            mx = fmaxf(mx, __shfl_xor_sync(0xffffffffu, mx, 2));
            const float m_old = m_s[q];
            const float m_new = fmaxf(m_old, mx);
            float sum = 0.f;
            #pragma unroll
            for (int t = 0; t < 16; t += 2) {
                const float p0 = __expf(Ss[q][r * 16 + t]     - m_new);
                const float p1 = __expf(Ss[q][r * 16 + t + 1] - m_new);
                sum += p0 + p1;
                __half h0, l0, h1, l1;
                split_h(p0 * 2048.f, h0, l0);
                split_h(p1 * 2048.f, h1, l1);
                const int chunk = 2 * r + (t >> 3);
                const int byte = q * 128 + ((chunk ^ (q & 7)) << 4) + ((t >> 1) & 3) * 4;
                *(uint32_t*)(smc + AT_PH + byte) = pack_h2(h0, h1);
                *(uint32_t*)(smc + AT_PL + byte) = pack_h2(l0, l1);
            }
            sum += __shfl_xor_sync(0xffffffffu, sum, 1);
            sum += __shfl_xor_sync(0xffffffffu, sum, 2);
            if (r == 0) {
                const float alpha = __expf(m_old - m_new);
                m_s[q] = m_new;
                l_s[q] = l_s[q] * alpha + sum;
                al_s[q] = alpha;
            }
        }
        __syncthreads();

        // ---- O = O*alpha + P V (64x64x64), 3xfp16 k16 ----
        #pragma unroll
        for (int mf = 0; mf < 2; mf++) {
            const int r0 = warp_m * 32 + mf * 16 + (lane >> 2);
            const float a0 = al_s[r0];
            const float a1 = al_s[r0 + 8];
            #pragma unroll
            for (int nf = 0; nf < 2; nf++) {
                o[mf][nf][0] *= a0; o[mf][nf][1] *= a0;
                o[mf][nf][2] *= a1; o[mf][nf][3] *= a1;
            }
        }
        #pragma unroll
        for (int ks = 0; ks < 4; ks++) {
            uint32_t aH[2][4], aL[2][4];
            #pragma unroll
            for (int mf = 0; mf < 2; mf++) {
                const int q = warp_m * 32 + mf * 16 + lm_row;
                const uint32_t off =
                    (uint32_t)(q * 128 + (((2 * ks + lm_csel) ^ (q & 7)) << 4));
                LDSM_X4(aH[mf][0], aH[mf][1], aH[mf][2], aH[mf][3], sm_base + AT_PH + off);
                LDSM_X4(aL[mf][0], aL[mf][1], aL[mf][2], aL[mf][3], sm_base + AT_PL + off);
            }
            #pragma unroll
            for (int nf = 0; nf < 2; nf++) {
                const int d = warp_n * 16 + nf * 8 + bq;
                const int i0 = d * 32 + (((2 * ks)     ^ (d & 7)) << 2) + bi;
                const int i1 = d * 32 + (((2 * ks + 1) ^ (d & 7)) << 2) + bi;
                const uint32_t bh0 = VTH32[i0], bh1 = VTH32[i1];
                const uint32_t bl0 = VTL32[i0], bl1 = VTL32[i1];
                #pragma unroll
                for (int mf = 0; mf < 2; mf++) {
                    MMA_F16(o[mf][nf], aH[mf][0], aH[mf][1], aH[mf][2], aH[mf][3], bh0, bh1);
                    MMA_F16(o[mf][nf], aH[mf][0], aH[mf][1], aH[mf][2], aH[mf][3], bl0, bl1);
                    MMA_F16(o[mf][nf], aL[mf][0], aL[mf][1], aL[mf][2], aL[mf][3], bh0, bh1);
                }
            }
        }
    }

    // ---- finalize: divide by l * 2048(P) * 256(V), write out ----
    #pragma unroll
    for (int mf = 0; mf < 2; mf++) {
        const int r0 = warp_m * 32 + mf * 16 + (lane >> 2);
        const float inv0 = 1.f / (l_s[r0] * 524288.f);
        const float inv1 = 1.f / (l_s[r0 + 8] * 524288.f);
        #pragma unroll
        for (int nf = 0; nf < 2; nf++) {
            const int col = h * HDIM + warp_n * 16 + nf * 8 + 2 * (lane & 3);
            *(float2*)(out + (size_t)(qrow0 + r0) * DMODEL + col) =
                make_float2(o[mf][nf][0] * inv0, o[mf][nf][1] * inv0);
            *(float2*)(out + (size_t)(qrow0 + r0 + 8) * DMODEL + col) =
                make_float2(o[mf][nf][2] * inv1, o[mf][nf][3] * inv1);
        }
    }
}

// ---------------------------------------------------------------------------
extern "C" void kernel_launch(void* const* d_in, const int* in_sizes, int n_in,
                              void* d_out, int out_size) {
    const float* x      = (const float*)d_in[0];   // [4096,1024]
    const float* w_qkv  = (const float*)d_in[1];   // [1024,3072]
    const float* w_out  = (const float*)d_in[2];   // [1024,1024]
    float* out = (float*)d_out;                    // [4096,1024]

    float *qkv, *attn;
    __half *xh, *xl, *wqh, *wql, *ath, *atl, *woh, *wol;
    cudaGetSymbolAddress((void**)&qkv, g_qkv);
    cudaGetSymbolAddress((void**)&attn, g_attn);
    cudaGetSymbolAddress((void**)&xh, g_xh);
    cudaGetSymbolAddress((void**)&xl, g_xl);
    cudaGetSymbolAddress((void**)&wqh, g_wqh);
    cudaGetSymbolAddress((void**)&wql, g_wql);
    cudaGetSymbolAddress((void**)&ath, g_ath);
    cudaGetSymbolAddress((void**)&atl, g_atl);
    cudaGetSymbolAddress((void**)&woh, g_woh);
    cudaGetSymbolAddress((void**)&wol, g_wol);

    const int gemm_smem = 65536;
    cudaFuncSetAttribute(gemm_f16x3, cudaFuncAttributeMaxDynamicSharedMemorySize,
                         gemm_smem);
    cudaFuncSetAttribute(attn_f16, cudaFuncAttributeMaxDynamicSharedMemorySize,
                         AT_SMEM);

    const int NX = SEQ * DMODEL;            // 4M elements
    const float oscale = 1.f / 65536.f;     // 256 * 256

    // split x and w_qkv
    split2h<<<NX / 4 / 256, 256>>>(x, xh, xl, NX);
    split2h_t<<<dim3(D3 / 32, DMODEL / 32), dim3(32, 8)>>>(w_qkv, wqh, wql,
                                                           DMODEL, D3);
    // 1) qkv = x @ w_qkv
    gemm_f16x3<<<dim3(D3 / 128, SEQ / 128), 256, gemm_smem>>>(
        xh, xl, wqh, wql, qkv, SEQ, D3, DMODEL, oscale);

    // 2) sliding-window attention
    attn_f16<<<dim3(8, NCHUNK, NHEAD), 256, AT_SMEM>>>(qkv, attn);

    // split attn and w_out
    split2h<<<NX / 4 / 256, 256>>>(attn, ath, atl, NX);
    split2h_t<<<dim3(DMODEL / 32, DMODEL / 32), dim3(32, 8)>>>(w_out, woh, wol,
                                                               DMODEL, DMODEL);
    // 3) out = attn @ w_out
    gemm_f16x3<<<dim3(DMODEL / 128, SEQ / 128), 256, gemm_smem>>>(
        ath, atl, woh, wol, out, SEQ, DMODEL, DMODEL, oscale);
}

// round 8
// speedup vs baseline: 1.7038x; 1.0129x over previous
#include <cuda_runtime.h>
#include <cuda_fp16.h>
#include <cstdint>

// Problem constants
#define SEQ    4096
#define DMODEL 1024
#define D3     3072
#define NHEAD  16
#define HDIM   64
#define WIN    512
#define NCHUNK 8

// Scratch (device globals: allocation-free per harness rules)
__device__ float  g_qkv[SEQ * D3];            // 48 MB
__device__ __half g_xh[SEQ * DMODEL];         // x split planes (scaled 256)
__device__ __half g_xl[SEQ * DMODEL];
__device__ __half g_wqh[D3 * DMODEL];         // w_qkv^T planes [N][K] (scaled 256)
__device__ __half g_wql[D3 * DMODEL];
__device__ __half g_ath[SEQ * DMODEL];        // attn split planes (scaled 256)
__device__ __half g_atl[SEQ * DMODEL];
__device__ __half g_woh[DMODEL * DMODEL];     // w_out^T planes [N][K]
__device__ __half g_wol[DMODEL * DMODEL];

// ---------------------------------------------------------------------------
// helpers
// ---------------------------------------------------------------------------
__device__ __forceinline__ void split_h(float x, __half& hi, __half& lo) {
    hi = __float2half_rn(x);
    lo = __float2half_rn(x - __half2float(hi));
}
__device__ __forceinline__ uint32_t pack_h2(__half a, __half b) {
    __half2 h = __halves2half2(a, b);
    return *reinterpret_cast<uint32_t*>(&h);
}
__device__ __forceinline__ uint32_t split_pack(float x, float y, uint32_t& lo) {
    __half hx, lx, hy, ly;
    split_h(x, hx, lx); split_h(y, hy, ly);
    lo = pack_h2(lx, ly);
    return pack_h2(hx, hy);
}

#define MMA_F16(d, a0, a1, a2, a3, b0, b1)                                     \
    asm volatile(                                                              \
        "mma.sync.aligned.m16n8k16.row.col.f32.f16.f16.f32 "                   \
        "{%0,%1,%2,%3}, {%4,%5,%6,%7}, {%8,%9}, {%0,%1,%2,%3};"                \
        : "+f"((d)[0]), "+f"((d)[1]), "+f"((d)[2]), "+f"((d)[3])               \
        : "r"(a0), "r"(a1), "r"(a2), "r"(a3), "r"(b0), "r"(b1))

#define LDSM_X4(r0, r1, r2, r3, addr)                                          \
    asm volatile("ldmatrix.sync.aligned.m8n8.x4.shared.b16 {%0,%1,%2,%3}, [%4];" \
        : "=r"(r0), "=r"(r1), "=r"(r2), "=r"(r3) : "r"(addr))

#define LDSM_X4_T(r0, r1, r2, r3, addr)                                        \
    asm volatile("ldmatrix.sync.aligned.m8n8.x4.trans.shared.b16 {%0,%1,%2,%3}, [%4];" \
        : "=r"(r0), "=r"(r1), "=r"(r2), "=r"(r3) : "r"(addr))

// ---------------------------------------------------------------------------
// Split kernels (scale by 256 exactly, then Dekker split to fp16 hi/lo)
// ---------------------------------------------------------------------------
__global__ __launch_bounds__(256) void split2h(const float* __restrict__ in,
                                               __half* __restrict__ hp,
                                               __half* __restrict__ lp, int n) {
    const int idx = (blockIdx.x * 256 + threadIdx.x) * 4;
    if (idx >= n) return;
    const float4 v = *(const float4*)(in + idx);
    uint32_t l0, l1;
    const uint32_t h0 = split_pack(v.x * 256.f, v.y * 256.f, l0);
    const uint32_t h1 = split_pack(v.z * 256.f, v.w * 256.f, l1);
    *(uint2*)(hp + idx) = make_uint2(h0, h1);
    *(uint2*)(lp + idx) = make_uint2(l0, l1);
}

// transpose + split: w[Kd][Nd] fp32 -> planes [Nd][Kd] fp16 (scaled 256)
__global__ void split2h_t(const float* __restrict__ w,
                          __half* __restrict__ th, __half* __restrict__ tl,
                          int Kd, int Nd) {
    __shared__ float tile[32][33];
    const int k0 = blockIdx.y * 32, n0 = blockIdx.x * 32;
    const int tx = threadIdx.x, ty = threadIdx.y;
    for (int r = ty; r < 32; r += 8)
        tile[r][tx] = w[(size_t)(k0 + r) * Nd + n0 + tx];
    __syncthreads();
    for (int r = ty; r < 32; r += 8) {
        __half h, l;
        split_h(tile[tx][r] * 256.f, h, l);
        const size_t o = (size_t)(n0 + r) * Kd + k0 + tx;
        th[o] = h; tl[o] = l;
    }
}

// ---------------------------------------------------------------------------
// 3xFP16 GEMM (m16n8k16) — unchanged from R7.
// ---------------------------------------------------------------------------
__global__ __launch_bounds__(256, 2) void gemm_f16x3(
    const __half* __restrict__ Ahg, const __half* __restrict__ Alg,
    const __half* __restrict__ Bhg, const __half* __restrict__ Blg,
    float* __restrict__ C, int M, int N, int K, float outscale) {
    extern __shared__ char smc[];

    const int tid  = threadIdx.x;
    const int lane = tid & 31;
    const int warp = tid >> 5;
    const int warp_m = warp >> 2;
    const int warp_n = warp & 3;

    const int m0 = blockIdx.y * 128;
    const int n0 = blockIdx.x * 128;

    const int lm_row  = (lane & 7) + ((lane >> 3) & 1) * 8;
    const int lm_csel = lane >> 4;
    const int bq = lane >> 2;
    const int bi = lane & 3;

    float acc[4][4][4] = {};

    const uint32_t sm_base = (uint32_t)__cvta_generic_to_shared(smc);
    const uint32_t ah_base = sm_base;
    const uint32_t al_base = sm_base + 16384;
    const uint32_t* BH32 = (const uint32_t*)(smc + 32768);
    const uint32_t* BL32 = (const uint32_t*)(smc + 49152);

    for (int k0 = 0; k0 < K; k0 += 64) {
        if (k0) __syncthreads();

        #pragma unroll
        for (int i = 0; i < 16; i++) {
            const int lin = tid + i * 256;
            const int pl  = lin >> 10;
            const int rem = lin & 1023;
            const int row = rem >> 3;
            const int ch  = rem & 7;
            const __half* src;
            if      (pl == 0) src = Ahg + (size_t)(m0 + row) * K;
            else if (pl == 1) src = Alg + (size_t)(m0 + row) * K;
            else if (pl == 2) src = Bhg + (size_t)(n0 + row) * K;
            else              src = Blg + (size_t)(n0 + row) * K;
            const uint4 v = *(const uint4*)(src + k0 + ch * 8);
            *(uint4*)(smc + pl * 16384 + row * 128 + ((ch ^ (row & 7)) << 4)) = v;
        }
        __syncthreads();

        #pragma unroll
        for (int s = 0; s < 4; s++) {
            uint32_t aH[4][4], aL[4][4];
            #pragma unroll
            for (int mf = 0; mf < 4; mf++) {
                const int m = warp_m * 64 + mf * 16 + lm_row;
                const uint32_t off =
                    (uint32_t)(m * 128 + (((2 * s + lm_csel) ^ (m & 7)) << 4));
                LDSM_X4(aH[mf][0], aH[mf][1], aH[mf][2], aH[mf][3], ah_base + off);
                LDSM_X4(aL[mf][0], aL[mf][1], aL[mf][2], aL[mf][3], al_base + off);
            }
            #pragma unroll
            for (int nf = 0; nf < 4; nf++) {
                const int n = warp_n * 32 + nf * 8 + bq;
                const int i0 = n * 32 + (((2 * s)     ^ (n & 7)) << 2) + bi;
                const int i1 = n * 32 + (((2 * s + 1) ^ (n & 7)) << 2) + bi;
                const uint32_t bh0 = BH32[i0], bh1 = BH32[i1];
                const uint32_t bl0 = BL32[i0], bl1 = BL32[i1];
                #pragma unroll
                for (int mf = 0; mf < 4; mf++) {
                    MMA_F16(acc[mf][nf], aH[mf][0], aH[mf][1], aH[mf][2], aH[mf][3], bh0, bh1);
                    MMA_F16(acc[mf][nf], aH[mf][0], aH[mf][1], aH[mf][2], aH[mf][3], bl0, bl1);
                    MMA_F16(acc[mf][nf], aL[mf][0], aL[mf][1], aL[mf][2], aL[mf][3], bh0, bh1);
                }
            }
        }
    }

    const int row_in = lane >> 2;
    const int col_in = 2 * (lane & 3);
    #pragma unroll
    for (int mf = 0; mf < 4; mf++) {
        const int gr = m0 + warp_m * 64 + mf * 16 + row_in;
        #pragma unroll
        for (int nf = 0; nf < 4; nf++) {
            const int gc = n0 + warp_n * 32 + nf * 8 + col_in;
            *(float2*)(C + (size_t)gr * N + gc) =
                make_float2(acc[mf][nf][0] * outscale, acc[mf][nf][1] * outscale);
            *(float2*)(C + (size_t)(gr + 8) * N + gc) =
                make_float2(acc[mf][nf][2] * outscale, acc[mf][nf][3] * outscale);
        }
    }
}

// ---------------------------------------------------------------------------
// Attention v2: FA2-style register softmax, 4 warps x (16q x 64j) per block.
// Q,K,V scaled x256 and split to fp16 hi/lo at smem store. S stays in regs;
// P (x2048) split+packed directly into MMA A fragments (C->A identity).
// V stored [j][d]; PV B-fragments via ldmatrix.x4.trans.
// Epilogue writes fp16 hi/lo planes (x256) for GEMM2 directly.
// smem: QH 0, QL 8K, KH 16K, KL 24K, VH 32K, VL 40K  (48 KB total)
// ---------------------------------------------------------------------------
#define AQH 0
#define AQL 8192
#define AKH 16384
#define AKL 24576
#define AVH 32768
#define AVL 40960
#define A_SMEM 49152

__global__ __launch_bounds__(128, 3) void attn_f16v2(
    const float* __restrict__ qkv,
    __half* __restrict__ ath, __half* __restrict__ atl) {
    extern __shared__ char smc[];

    const int qt = blockIdx.x;     // 0..7
    const int c  = blockIdx.y;     // 0..7
    const int h  = blockIdx.z;     // 0..15
    const int tid  = threadIdx.x;
    const int lane = tid & 31;
    const int w    = tid >> 5;     // warp 0..3, owns q rows w*16..w*16+15

    const int q0 = qt * 64;
    const int qrow0 = c * WIN + q0;

    const int lm_row  = (lane & 7) + ((lane >> 3) & 1) * 8;
    const int lm_csel = lane >> 4;
    const uint32_t sb = (uint32_t)__cvta_generic_to_shared(smc);

    // ---- load Q tile (64 rows), scale x256, split ----
    {
        const int q = tid >> 1;
        const float* src = qkv + (size_t)(qrow0 + q) * D3 + h * HDIM;
        #pragma unroll
        for (int i = 0; i < 8; i++) {
            const int cd = (tid & 1) * 8 + i;     // float4 chunk 0..15
            const float4 v = *(const float4*)(src + cd * 4);
            uint32_t l0, l1;
            const uint32_t h0 = split_pack(v.x * 256.f, v.y * 256.f, l0);
            const uint32_t h1 = split_pack(v.z * 256.f, v.w * 256.f, l1);
            const int byte = q * 128 + (((cd >> 1) ^ (q & 7)) << 4) + (cd & 1) * 8;
            *(uint2*)(smc + AQH + byte) = make_uint2(h0, h1);
            *(uint2*)(smc + AQL + byte) = make_uint2(l0, l1);
        }
    }
    __syncthreads();

    // ---- preload Q fragments (held in registers all kernel) ----
    uint32_t qH[4][4], qL[4][4];
    {
        const int q = w * 16 + lm_row;
        #pragma unroll
        for (int ks = 0; ks < 4; ks++) {
            const uint32_t off =
                (uint32_t)(q * 128 + (((2 * ks + lm_csel) ^ (q & 7)) << 4));
            LDSM_X4(qH[ks][0], qH[ks][1], qH[ks][2], qH[ks][3], sb + AQH + off);
            LDSM_X4(qL[ks][0], qL[ks][1], qL[ks][2], qL[ks][3], sb + AQL + off);
        }
    }

    float o[8][4] = {};
    float m0 = -1e30f, m1 = -1e30f, l0r = 0.f, l1r = 0.f;

    const int kb_start = (c == 0) ? (WIN / 64) : 0;
    const int kb_end = ((q0 + 63 + WIN) >> 6) + 1;   // exclusive, <= 16

    const int rq0 = q0 + w * 16 + (lane >> 2);   // query pos within chunk
    const int rq1 = rq0 + 8;

    for (int kb = kb_start; kb < kb_end; kb++) {
        const int j0 = kb * 64;
        __syncthreads();

        // ---- load K,V (64 rows), scale x256, split; both stored [j][d] ----
        {
            const int j = tid >> 1;
            const int krow = c * WIN + j0 - WIN + j;
            const float* ksrc = qkv + (size_t)krow * D3 + DMODEL + h * HDIM;
            const float* vsrc = qkv + (size_t)krow * D3 + 2 * DMODEL + h * HDIM;
            #pragma unroll
            for (int i = 0; i < 8; i++) {
                const int cd = (tid & 1) * 8 + i;
                const int byte = j * 128 + (((cd >> 1) ^ (j & 7)) << 4) + (cd & 1) * 8;
                const float4 kv = *(const float4*)(ksrc + cd * 4);
                uint32_t kl0, kl1;
                const uint32_t kh0 = split_pack(kv.x * 256.f, kv.y * 256.f, kl0);
                const uint32_t kh1 = split_pack(kv.z * 256.f, kv.w * 256.f, kl1);
                *(uint2*)(smc + AKH + byte) = make_uint2(kh0, kh1);
                *(uint2*)(smc + AKL + byte) = make_uint2(kl0, kl1);
                const float4 vv = *(const float4*)(vsrc + cd * 4);
                uint32_t vl0, vl1;
                const uint32_t vh0 = split_pack(vv.x * 256.f, vv.y * 256.f, vl0);
                const uint32_t vh1 = split_pack(vv.z * 256.f, vv.w * 256.f, vl1);
                *(uint2*)(smc + AVH + byte) = make_uint2(vh0, vh1);
                *(uint2*)(smc + AVL + byte) = make_uint2(vl0, vl1);
            }
        }
        __syncthreads();

        // ---- S = Q K^T : warp computes 16q x 64j, S in registers ----
        float s[8][4] = {};
        const int g  = lane >> 3;      // matrix index within x4
        const int gs = g >> 1;         // sub-frag select
        const int gc = g & 1;          // k-chunk select
        #pragma unroll
        for (int ks = 0; ks < 4; ks++) {
            #pragma unroll
            for (int p = 0; p < 4; p++) {
                // B frags for nf = 2p, 2p+1 from K[j][d] via normal ldmatrix
                const int jr = 8 * (2 * p + gs) + (lane & 7);
                const uint32_t off =
                    (uint32_t)(jr * 128 + (((2 * ks + gc) ^ (jr & 7)) << 4));
                uint32_t rH[4], rL[4];
                LDSM_X4(rH[0], rH[1], rH[2], rH[3], sb + AKH + off);
                LDSM_X4(rL[0], rL[1], rL[2], rL[3], sb + AKL + off);
                #pragma unroll
                for (int s2 = 0; s2 < 2; s2++) {
                    const int nf = 2 * p + s2;
                    MMA_F16(s[nf], qH[ks][0], qH[ks][1], qH[ks][2], qH[ks][3], rH[2*s2], rH[2*s2+1]);
                    MMA_F16(s[nf], qH[ks][0], qH[ks][1], qH[ks][2], qH[ks][3], rL[2*s2], rL[2*s2+1]);
                    MMA_F16(s[nf], qL[ks][0], qL[ks][1], qL[ks][2], qL[ks][3], rH[2*s2], rH[2*s2+1]);
                }
            }
        }

        // ---- mask + scale (0.125/65536) in registers ----
        const float sc = 0.125f / 65536.f;
        #pragma unroll
        for (int nf = 0; nf < 8; nf++) {
            const int col = j0 + nf * 8 + 2 * (lane & 3);
            s[nf][0] = (rq0 + WIN >= col)     ? s[nf][0] * sc : -1e30f;
            s[nf][1] = (rq0 + WIN >= col + 1) ? s[nf][1] * sc : -1e30f;
            s[nf][2] = (rq1 + WIN >= col)     ? s[nf][2] * sc : -1e30f;
            s[nf][3] = (rq1 + WIN >= col + 1) ? s[nf][3] * sc : -1e30f;
        }

        // ---- register online softmax (rows rq0, rq1) ----
        float mx0 = -1e30f, mx1 = -1e30f;
        #pragma unroll
        for (int nf = 0; nf < 8; nf++) {
            mx0 = fmaxf(mx0, fmaxf(s[nf][0], s[nf][1]));
            mx1 = fmaxf(mx1, fmaxf(s[nf][2], s[nf][3]));
        }
        mx0 = fmaxf(mx0, __shfl_xor_sync(0xffffffffu, mx0, 1));
        mx0 = fmaxf(mx0, __shfl_xor_sync(0xffffffffu, mx0, 2));
        mx1 = fmaxf(mx1, __shfl_xor_sync(0xffffffffu, mx1, 1));
        mx1 = fmaxf(mx1, __shfl_xor_sync(0xffffffffu, mx1, 2));
        const float m0n = fmaxf(m0, mx0);
        const float m1n = fmaxf(m1, mx1);
        const float a0 = __expf(m0 - m0n);
        const float a1 = __expf(m1 - m1n);
        float sum0 = 0.f, sum1 = 0.f;
        #pragma unroll
        for (int nf = 0; nf < 8; nf++) {
            s[nf][0] = __expf(s[nf][0] - m0n);
            s[nf][1] = __expf(s[nf][1] - m0n);
            s[nf][2] = __expf(s[nf][2] - m1n);
            s[nf][3] = __expf(s[nf][3] - m1n);
            sum0 += s[nf][0] + s[nf][1];
            sum1 += s[nf][2] + s[nf][3];
        }
        sum0 += __shfl_xor_sync(0xffffffffu, sum0, 1);
        sum0 += __shfl_xor_sync(0xffffffffu, sum0, 2);
        sum1 += __shfl_xor_sync(0xffffffffu, sum1, 1);
        sum1 += __shfl_xor_sync(0xffffffffu, sum1, 2);
        m0 = m0n; m1 = m1n;
        l0r = l0r * a0 + sum0;
        l1r = l1r * a1 + sum1;

        // ---- rescale O, build P A-fragments (x2048, split hi/lo) ----
        #pragma unroll
        for (int nf = 0; nf < 8; nf++) {
            o[nf][0] *= a0; o[nf][1] *= a0;
            o[nf][2] *= a1; o[nf][3] *= a1;
        }
        uint32_t pH[4][4], pL[4][4];
        #pragma unroll
        for (int ks = 0; ks < 4; ks++) {
            pH[ks][0] = split_pack(s[2*ks][0]   * 2048.f, s[2*ks][1]   * 2048.f, pL[ks][0]);
            pH[ks][1] = split_pack(s[2*ks][2]   * 2048.f, s[2*ks][3]   * 2048.f, pL[ks][1]);
            pH[ks][2] = split_pack(s[2*ks+1][0] * 2048.f, s[2*ks+1][1] * 2048.f, pL[ks][2]);
            pH[ks][3] = split_pack(s[2*ks+1][2] * 2048.f, s[2*ks+1][3] * 2048.f, pL[ks][3]);
        }

        // ---- O += P V : B frags via ldmatrix.trans from V[j][d] ----
        #pragma unroll
        for (int ks = 0; ks < 4; ks++) {
            #pragma unroll
            for (int p2 = 0; p2 < 4; p2++) {
                const int jr = 16 * ks + 8 * gc + (lane & 7);
                const int ch = 2 * p2 + gs;
                const uint32_t off =
                    (uint32_t)(jr * 128 + ((ch ^ (jr & 7)) << 4));
                uint32_t rH[4], rL[4];
                LDSM_X4_T(rH[0], rH[1], rH[2], rH[3], sb + AVH + off);
                LDSM_X4_T(rL[0], rL[1], rL[2], rL[3], sb + AVL + off);
                #pragma unroll
                for (int s2 = 0; s2 < 2; s2++) {
                    const int nf = 2 * p2 + s2;
                    MMA_F16(o[nf], pH[ks][0], pH[ks][1], pH[ks][2], pH[ks][3], rH[2*s2], rH[2*s2+1]);
                    MMA_F16(o[nf], pH[ks][0], pH[ks][1], pH[ks][2], pH[ks][3], rL[2*s2], rL[2*s2+1]);
                    MMA_F16(o[nf], pL[ks][0], pL[ks][1], pL[ks][2], pL[ks][3], rH[2*s2], rH[2*s2+1]);
                }
            }
        }
    }

    // ---- finalize: v = o / (l * 524288); write (v*256) split hi/lo planes ----
    // combined per-element factor for the planes: 1 / (l * 2048)
    const float inv0 = 1.f / (l0r * 2048.f);
    const float inv1 = 1.f / (l1r * 2048.f);
    const int grow0 = qrow0 + w * 16 + (lane >> 2);
    const int grow1 = grow0 + 8;
    #pragma unroll
    for (int nf = 0; nf < 8; nf++) {
        const int dcol = h * HDIM + nf * 8 + 2 * (lane & 3);
        uint32_t lo;
        uint32_t hi = split_pack(o[nf][0] * inv0, o[nf][1] * inv0, lo);
        *(uint32_t*)(ath + (size_t)grow0 * DMODEL + dcol) = hi;
        *(uint32_t*)(atl + (size_t)grow0 * DMODEL + dcol) = lo;
        hi = split_pack(o[nf][2] * inv1, o[nf][3] * inv1, lo);
        *(uint32_t*)(ath + (size_t)grow1 * DMODEL + dcol) = hi;
        *(uint32_t*)(atl + (size_t)grow1 * DMODEL + dcol) = lo;
    }
}

// ---------------------------------------------------------------------------
extern "C" void kernel_launch(void* const* d_in, const int* in_sizes, int n_in,
                              void* d_out, int out_size) {
    const float* x      = (const float*)d_in[0];   // [4096,1024]
    const float* w_qkv  = (const float*)d_in[1];   // [1024,3072]
    const float* w_out  = (const float*)d_in[2];   // [1024,1024]
    float* out = (float*)d_out;                    // [4096,1024]

    float* qkv;
    __half *xh, *xl, *wqh, *wql, *ath, *atl, *woh, *wol;
    cudaGetSymbolAddress((void**)&qkv, g_qkv);
    cudaGetSymbolAddress((void**)&xh, g_xh);
    cudaGetSymbolAddress((void**)&xl, g_xl);
    cudaGetSymbolAddress((void**)&wqh, g_wqh);
    cudaGetSymbolAddress((void**)&wql, g_wql);
    cudaGetSymbolAddress((void**)&ath, g_ath);
    cudaGetSymbolAddress((void**)&atl, g_atl);
    cudaGetSymbolAddress((void**)&woh, g_woh);
    cudaGetSymbolAddress((void**)&wol, g_wol);

    const int gemm_smem = 65536;
    cudaFuncSetAttribute(gemm_f16x3, cudaFuncAttributeMaxDynamicSharedMemorySize,
                         gemm_smem);
    cudaFuncSetAttribute(attn_f16v2, cudaFuncAttributeMaxDynamicSharedMemorySize,
                         A_SMEM);

    const int NX = SEQ * DMODEL;            // 4M elements
    const float oscale = 1.f / 65536.f;     // undo 256 * 256

    // split x and w_qkv
    split2h<<<NX / 4 / 256, 256>>>(x, xh, xl, NX);
    split2h_t<<<dim3(D3 / 32, DMODEL / 32), dim3(32, 8)>>>(w_qkv, wqh, wql,
                                                           DMODEL, D3);
    // 1) qkv = x @ w_qkv
    gemm_f16x3<<<dim3(D3 / 128, SEQ / 128), 256, gemm_smem>>>(
        xh, xl, wqh, wql, qkv, SEQ, D3, DMODEL, oscale);

    // 2) sliding-window attention (writes split planes for GEMM2 directly)
    attn_f16v2<<<dim3(8, NCHUNK, NHEAD), 128, A_SMEM>>>(qkv, ath, atl);

    // split w_out
    split2h_t<<<dim3(DMODEL / 32, DMODEL / 32), dim3(32, 8)>>>(w_out, woh, wol,
                                                               DMODEL, DMODEL);
    // 3) out = attn @ w_out
    gemm_f16x3<<<dim3(DMODEL / 128, SEQ / 128), 256, gemm_smem>>>(
        ath, atl, woh, wol, out, SEQ, DMODEL, DMODEL, oscale);
}

// round 9
// speedup vs baseline: 1.8855x; 1.1066x over previous
#include <cuda_runtime.h>
#include <cuda_fp16.h>
#include <cstdint>

// Problem constants
#define SEQ    4096
#define DMODEL 1024
#define D3     3072
#define NHEAD  16
#define HDIM   64
#define WIN    512
#define NCHUNK 8

// Scratch (device globals: allocation-free per harness rules)
__device__ __half g_qkvh[SEQ * D3];           // qkv hi plane (x256)
__device__ __half g_qkvl[SEQ * D3];           // qkv lo plane
__device__ __half g_xh[SEQ * DMODEL];         // x split planes (scaled 256)
__device__ __half g_xl[SEQ * DMODEL];
__device__ __half g_wqh[D3 * DMODEL];         // w_qkv^T planes [N][K] (scaled 256)
__device__ __half g_wql[D3 * DMODEL];
__device__ __half g_ath[SEQ * DMODEL];        // attn split planes (scaled 256)
__device__ __half g_atl[SEQ * DMODEL];
__device__ __half g_woh[DMODEL * DMODEL];     // w_out^T planes [N][K]
__device__ __half g_wol[DMODEL * DMODEL];

// ---------------------------------------------------------------------------
// helpers
// ---------------------------------------------------------------------------
__device__ __forceinline__ void split_h(float x, __half& hi, __half& lo) {
    hi = __float2half_rn(x);
    lo = __float2half_rn(x - __half2float(hi));
}
__device__ __forceinline__ uint32_t pack_h2(__half a, __half b) {
    __half2 h = __halves2half2(a, b);
    return *reinterpret_cast<uint32_t*>(&h);
}
__device__ __forceinline__ uint32_t split_pack(float x, float y, uint32_t& lo) {
    __half hx, lx, hy, ly;
    split_h(x, hx, lx); split_h(y, hy, ly);
    lo = pack_h2(lx, ly);
    return pack_h2(hx, hy);
}

#define MMA_F16(d, a0, a1, a2, a3, b0, b1)                                     \
    asm volatile(                                                              \
        "mma.sync.aligned.m16n8k16.row.col.f32.f16.f16.f32 "                   \
        "{%0,%1,%2,%3}, {%4,%5,%6,%7}, {%8,%9}, {%0,%1,%2,%3};"                \
        : "+f"((d)[0]), "+f"((d)[1]), "+f"((d)[2]), "+f"((d)[3])               \
        : "r"(a0), "r"(a1), "r"(a2), "r"(a3), "r"(b0), "r"(b1))

#define LDSM_X4(r0, r1, r2, r3, addr)                                          \
    asm volatile("ldmatrix.sync.aligned.m8n8.x4.shared.b16 {%0,%1,%2,%3}, [%4];" \
        : "=r"(r0), "=r"(r1), "=r"(r2), "=r"(r3) : "r"(addr))

#define LDSM_X4_T(r0, r1, r2, r3, addr)                                        \
    asm volatile("ldmatrix.sync.aligned.m8n8.x4.trans.shared.b16 {%0,%1,%2,%3}, [%4];" \
        : "=r"(r0), "=r"(r1), "=r"(r2), "=r"(r3) : "r"(addr))

// ---------------------------------------------------------------------------
// Split kernels
// ---------------------------------------------------------------------------
__global__ __launch_bounds__(256) void split2h(const float* __restrict__ in,
                                               __half* __restrict__ hp,
                                               __half* __restrict__ lp, int n) {
    const int idx = (blockIdx.x * 256 + threadIdx.x) * 4;
    if (idx >= n) return;
    const float4 v = *(const float4*)(in + idx);
    uint32_t l0, l1;
    const uint32_t h0 = split_pack(v.x * 256.f, v.y * 256.f, l0);
    const uint32_t h1 = split_pack(v.z * 256.f, v.w * 256.f, l1);
    *(uint2*)(hp + idx) = make_uint2(h0, h1);
    *(uint2*)(lp + idx) = make_uint2(l0, l1);
}

__global__ void split2h_t(const float* __restrict__ w,
                          __half* __restrict__ th, __half* __restrict__ tl,
                          int Kd, int Nd) {
    __shared__ float tile[32][33];
    const int k0 = blockIdx.y * 32, n0 = blockIdx.x * 32;
    const int tx = threadIdx.x, ty = threadIdx.y;
    for (int r = ty; r < 32; r += 8)
        tile[r][tx] = w[(size_t)(k0 + r) * Nd + n0 + tx];
    __syncthreads();
    for (int r = ty; r < 32; r += 8) {
        __half h, l;
        split_h(tile[tx][r] * 256.f, h, l);
        const size_t o = (size_t)(n0 + r) * Kd + k0 + tx;
        th[o] = h; tl[o] = l;
    }
}

// ---------------------------------------------------------------------------
// 3xFP16 GEMM (m16n8k16). If SPLIT_OUT, epilogue writes x256-scaled fp16
// hi/lo planes (Ch/Cl); otherwise fp32 to Cf.
// ---------------------------------------------------------------------------
template <bool SPLIT_OUT>
__global__ __launch_bounds__(256, 2) void gemm_f16x3(
    const __half* __restrict__ Ahg, const __half* __restrict__ Alg,
    const __half* __restrict__ Bhg, const __half* __restrict__ Blg,
    float* __restrict__ Cf, __half* __restrict__ Ch, __half* __restrict__ Cl,
    int M, int N, int K, float outscale) {
    extern __shared__ char smc[];

    const int tid  = threadIdx.x;
    const int lane = tid & 31;
    const int warp = tid >> 5;
    const int warp_m = warp >> 2;
    const int warp_n = warp & 3;

    const int m0 = blockIdx.y * 128;
    const int n0 = blockIdx.x * 128;

    const int lm_row  = (lane & 7) + ((lane >> 3) & 1) * 8;
    const int lm_csel = lane >> 4;
    const int bq = lane >> 2;
    const int bi = lane & 3;

    float acc[4][4][4] = {};

    const uint32_t sm_base = (uint32_t)__cvta_generic_to_shared(smc);
    const uint32_t ah_base = sm_base;
    const uint32_t al_base = sm_base + 16384;
    const uint32_t* BH32 = (const uint32_t*)(smc + 32768);
    const uint32_t* BL32 = (const uint32_t*)(smc + 49152);

    for (int k0 = 0; k0 < K; k0 += 64) {
        if (k0) __syncthreads();

        #pragma unroll
        for (int i = 0; i < 16; i++) {
            const int lin = tid + i * 256;
            const int pl  = lin >> 10;
            const int rem = lin & 1023;
            const int row = rem >> 3;
            const int ch  = rem & 7;
            const __half* src;
            if      (pl == 0) src = Ahg + (size_t)(m0 + row) * K;
            else if (pl == 1) src = Alg + (size_t)(m0 + row) * K;
            else if (pl == 2) src = Bhg + (size_t)(n0 + row) * K;
            else              src = Blg + (size_t)(n0 + row) * K;
            const uint4 v = *(const uint4*)(src + k0 + ch * 8);
            *(uint4*)(smc + pl * 16384 + row * 128 + ((ch ^ (row & 7)) << 4)) = v;
        }
        __syncthreads();

        #pragma unroll
        for (int s = 0; s < 4; s++) {
            uint32_t aH[4][4], aL[4][4];
            #pragma unroll
            for (int mf = 0; mf < 4; mf++) {
                const int m = warp_m * 64 + mf * 16 + lm_row;
                const uint32_t off =
                    (uint32_t)(m * 128 + (((2 * s + lm_csel) ^ (m & 7)) << 4));
                LDSM_X4(aH[mf][0], aH[mf][1], aH[mf][2], aH[mf][3], ah_base + off);
                LDSM_X4(aL[mf][0], aL[mf][1], aL[mf][2], aL[mf][3], al_base + off);
            }
            #pragma unroll
            for (int nf = 0; nf < 4; nf++) {
                const int n = warp_n * 32 + nf * 8 + bq;
                const int i0 = n * 32 + (((2 * s)     ^ (n & 7)) << 2) + bi;
                const int i1 = n * 32 + (((2 * s + 1) ^ (n & 7)) << 2) + bi;
                const uint32_t bh0 = BH32[i0], bh1 = BH32[i1];
                const uint32_t bl0 = BL32[i0], bl1 = BL32[i1];
                #pragma unroll
                for (int mf = 0; mf < 4; mf++) {
                    MMA_F16(acc[mf][nf], aH[mf][0], aH[mf][1], aH[mf][2], aH[mf][3], bh0, bh1);
                    MMA_F16(acc[mf][nf], aH[mf][0], aH[mf][1], aH[mf][2], aH[mf][3], bl0, bl1);
                    MMA_F16(acc[mf][nf], aL[mf][0], aL[mf][1], aL[mf][2], aL[mf][3], bh0, bh1);
                }
            }
        }
    }

    const int row_in = lane >> 2;
    const int col_in = 2 * (lane & 3);
    #pragma unroll
    for (int mf = 0; mf < 4; mf++) {
        const int gr = m0 + warp_m * 64 + mf * 16 + row_in;
        #pragma unroll
        for (int nf = 0; nf < 4; nf++) {
            const int gc = n0 + warp_n * 32 + nf * 8 + col_in;
            if (SPLIT_OUT) {
                uint32_t lo;
                uint32_t hi = split_pack(acc[mf][nf][0] * outscale,
                                         acc[mf][nf][1] * outscale, lo);
                *(uint32_t*)(Ch + (size_t)gr * N + gc) = hi;
                *(uint32_t*)(Cl + (size_t)gr * N + gc) = lo;
                hi = split_pack(acc[mf][nf][2] * outscale,
                                acc[mf][nf][3] * outscale, lo);
                *(uint32_t*)(Ch + (size_t)(gr + 8) * N + gc) = hi;
                *(uint32_t*)(Cl + (size_t)(gr + 8) * N + gc) = lo;
            } else {
                *(float2*)(Cf + (size_t)gr * N + gc) =
                    make_float2(acc[mf][nf][0] * outscale, acc[mf][nf][1] * outscale);
                *(float2*)(Cf + (size_t)(gr + 8) * N + gc) =
                    make_float2(acc[mf][nf][2] * outscale, acc[mf][nf][3] * outscale);
            }
        }
    }
}

// ---------------------------------------------------------------------------
// Attention v3: 128 q-rows/CTA, 4 warps x 32q (2 m-frags each). FA2 register
// softmax. Inputs are pre-split x256 fp16 hi/lo planes -> loaders are pure
// uint4 copies. V fragments shared across both m-frags in the PV loop.
// smem: QH 0 (16K), QL 16K, KH 32K, KL 40K, VH 48K, VL 56K = 64 KB.
// ---------------------------------------------------------------------------
#define AQH 0
#define AQL 16384
#define AKV 32768
#define A_SMEM 65536

__global__ __launch_bounds__(128, 2) void attn_f16v3(
    const __half* __restrict__ qkvh, const __half* __restrict__ qkvl,
    __half* __restrict__ ath, __half* __restrict__ atl) {
    extern __shared__ char smc[];

    const int qt = blockIdx.x;     // 0..3 (128-q tile)
    const int c  = blockIdx.y;     // 0..7
    const int h  = blockIdx.z;     // 0..15
    const int tid  = threadIdx.x;
    const int lane = tid & 31;
    const int w    = tid >> 5;     // warp 0..3, owns q rows w*32..w*32+31

    const int q0 = qt * 128;
    const int qrow0 = c * WIN + q0;

    const int lm_row  = (lane & 7) + ((lane >> 3) & 1) * 8;
    const int lm_csel = lane >> 4;
    const int gs = (lane >> 4) & 1;   // = (lane>>3)>>1
    const int gc = (lane >> 3) & 1;
    const uint32_t sb = (uint32_t)__cvta_generic_to_shared(smc);

    // ---- load Q tile (128 rows x 64 fp16, hi+lo) : pure copy ----
    #pragma unroll
    for (int i = 0; i < 16; i++) {
        const int lin = tid + i * 128;      // 0..2047
        const int pl  = lin >> 10;          // 0:H 1:L
        const int rem = lin & 1023;
        const int row = rem >> 3;
        const int ch  = rem & 7;
        const __half* src = (pl ? qkvl : qkvh)
            + (size_t)(qrow0 + row) * D3 + h * HDIM + ch * 8;
        const uint4 v = *(const uint4*)src;
        *(uint4*)(smc + pl * 16384 + row * 128 + ((ch ^ (row & 7)) << 4)) = v;
    }
    __syncthreads();

    float o[2][8][4] = {};
    float mrow[2][2] = {{-1e30f, -1e30f}, {-1e30f, -1e30f}};
    float lrow[2][2] = {{0.f, 0.f}, {0.f, 0.f}};

    const int kb_start = (c == 0) ? (WIN / 64) : 0;
    const int kb_end = ((q0 + 127 + WIN) >> 6) + 1;   // exclusive, <= 16

    for (int kb = kb_start; kb < kb_end; kb++) {
        const int j0 = kb * 64;
        __syncthreads();

        // ---- load K,V (64 rows, hi+lo) : pure copy from planes ----
        #pragma unroll
        for (int i = 0; i < 16; i++) {
            const int lin = tid + i * 128;    // 0..2047
            const int pl  = lin >> 9;         // 0:KH 1:KL 2:VH 3:VL
            const int rem = lin & 511;
            const int row = rem >> 3;
            const int ch  = rem & 7;
            const int krow = c * WIN + j0 - WIN + row;
            const __half* src = ((pl & 1) ? qkvl : qkvh)
                + (size_t)krow * D3 + ((pl >> 1) ? 2 * DMODEL : DMODEL)
                + h * HDIM + ch * 8;
            const uint4 v = *(const uint4*)src;
            *(uint4*)(smc + AKV + pl * 8192 + row * 128 + ((ch ^ (row & 7)) << 4)) = v;
        }
        __syncthreads();

        // ---- S = Q K^T : 32q x 64j per warp, S in registers ----
        float s[2][8][4] = {};
        #pragma unroll
        for (int ks = 0; ks < 4; ks++) {
            uint32_t qf[2][2][4];   // [mf][plane][reg]
            #pragma unroll
            for (int mf = 0; mf < 2; mf++) {
                const int qr = w * 32 + mf * 16 + lm_row;
                const uint32_t off =
                    (uint32_t)(qr * 128 + (((2 * ks + lm_csel) ^ (qr & 7)) << 4));
                LDSM_X4(qf[mf][0][0], qf[mf][0][1], qf[mf][0][2], qf[mf][0][3], sb + AQH + off);
                LDSM_X4(qf[mf][1][0], qf[mf][1][1], qf[mf][1][2], qf[mf][1][3], sb + AQL + off);
            }
            #pragma unroll
            for (int p = 0; p < 4; p++) {
                const int jr = 8 * (2 * p + gs) + (lane & 7);
                const uint32_t off =
                    (uint32_t)(jr * 128 + (((2 * ks + gc) ^ (jr & 7)) << 4));
                uint32_t rH[4], rL[4];
                LDSM_X4(rH[0], rH[1], rH[2], rH[3], sb + AKV + off);          // KH
                LDSM_X4(rL[0], rL[1], rL[2], rL[3], sb + AKV + 8192 + off);   // KL
                #pragma unroll
                for (int mf = 0; mf < 2; mf++)
                    #pragma unroll
                    for (int s2 = 0; s2 < 2; s2++) {
                        const int nf = 2 * p + s2;
                        MMA_F16(s[mf][nf], qf[mf][0][0], qf[mf][0][1], qf[mf][0][2], qf[mf][0][3], rH[2*s2], rH[2*s2+1]);
                        MMA_F16(s[mf][nf], qf[mf][0][0], qf[mf][0][1], qf[mf][0][2], qf[mf][0][3], rL[2*s2], rL[2*s2+1]);
                        MMA_F16(s[mf][nf], qf[mf][1][0], qf[mf][1][1], qf[mf][1][2], qf[mf][1][3], rH[2*s2], rH[2*s2+1]);
                    }
            }
        }

        // ---- mask + register online softmax + build P frags (per mf) ----
        uint32_t pH[2][4][4], pL[2][4][4];
        #pragma unroll
        for (int mf = 0; mf < 2; mf++) {
            const int rq0 = q0 + w * 32 + mf * 16 + (lane >> 2);
            const int rq1 = rq0 + 8;
            const float sc = 0.125f / 65536.f;
            #pragma unroll
            for (int nf = 0; nf < 8; nf++) {
                const int col = j0 + nf * 8 + 2 * (lane & 3);
                s[mf][nf][0] = (rq0 + WIN >= col)     ? s[mf][nf][0] * sc : -1e30f;
                s[mf][nf][1] = (rq0 + WIN >= col + 1) ? s[mf][nf][1] * sc : -1e30f;
                s[mf][nf][2] = (rq1 + WIN >= col)     ? s[mf][nf][2] * sc : -1e30f;
                s[mf][nf][3] = (rq1 + WIN >= col + 1) ? s[mf][nf][3] * sc : -1e30f;
            }
            float mx0 = -1e30f, mx1 = -1e30f;
            #pragma unroll
            for (int nf = 0; nf < 8; nf++) {
                mx0 = fmaxf(mx0, fmaxf(s[mf][nf][0], s[mf][nf][1]));
                mx1 = fmaxf(mx1, fmaxf(s[mf][nf][2], s[mf][nf][3]));
            }
            mx0 = fmaxf(mx0, __shfl_xor_sync(0xffffffffu, mx0, 1));
            mx0 = fmaxf(mx0, __shfl_xor_sync(0xffffffffu, mx0, 2));
            mx1 = fmaxf(mx1, __shfl_xor_sync(0xffffffffu, mx1, 1));
            mx1 = fmaxf(mx1, __shfl_xor_sync(0xffffffffu, mx1, 2));
            const float m0n = fmaxf(mrow[mf][0], mx0);
            const float m1n = fmaxf(mrow[mf][1], mx1);
            const float a0 = __expf(mrow[mf][0] - m0n);
            const float a1 = __expf(mrow[mf][1] - m1n);
            float sum0 = 0.f, sum1 = 0.f;
            #pragma unroll
            for (int nf = 0; nf < 8; nf++) {
                s[mf][nf][0] = __expf(s[mf][nf][0] - m0n);
                s[mf][nf][1] = __expf(s[mf][nf][1] - m0n);
                s[mf][nf][2] = __expf(s[mf][nf][2] - m1n);
                s[mf][nf][3] = __expf(s[mf][nf][3] - m1n);
                sum0 += s[mf][nf][0] + s[mf][nf][1];
                sum1 += s[mf][nf][2] + s[mf][nf][3];
            }
            sum0 += __shfl_xor_sync(0xffffffffu, sum0, 1);
            sum0 += __shfl_xor_sync(0xffffffffu, sum0, 2);
            sum1 += __shfl_xor_sync(0xffffffffu, sum1, 1);
            sum1 += __shfl_xor_sync(0xffffffffu, sum1, 2);
            mrow[mf][0] = m0n; mrow[mf][1] = m1n;
            lrow[mf][0] = lrow[mf][0] * a0 + sum0;
            lrow[mf][1] = lrow[mf][1] * a1 + sum1;
            #pragma unroll
            for (int nf = 0; nf < 8; nf++) {
                o[mf][nf][0] *= a0; o[mf][nf][1] *= a0;
                o[mf][nf][2] *= a1; o[mf][nf][3] *= a1;
            }
            #pragma unroll
            for (int ks = 0; ks < 4; ks++) {
                pH[mf][ks][0] = split_pack(s[mf][2*ks][0]   * 2048.f, s[mf][2*ks][1]   * 2048.f, pL[mf][ks][0]);
                pH[mf][ks][1] = split_pack(s[mf][2*ks][2]   * 2048.f, s[mf][2*ks][3]   * 2048.f, pL[mf][ks][1]);
                pH[mf][ks][2] = split_pack(s[mf][2*ks+1][0] * 2048.f, s[mf][2*ks+1][1] * 2048.f, pL[mf][ks][2]);
                pH[mf][ks][3] = split_pack(s[mf][2*ks+1][2] * 2048.f, s[mf][2*ks+1][3] * 2048.f, pL[mf][ks][3]);
            }
        }

        // ---- O += P V : V frags (trans ldmatrix) shared across both mf ----
        #pragma unroll
        for (int ks = 0; ks < 4; ks++) {
            #pragma unroll
            for (int p2 = 0; p2 < 4; p2++) {
                const int jr = 16 * ks + 8 * gc + (lane & 7);
                const int ch = 2 * p2 + gs;
                const uint32_t off =
                    (uint32_t)(jr * 128 + ((ch ^ (jr & 7)) << 4));
                uint32_t rH[4], rL[4];
                LDSM_X4_T(rH[0], rH[1], rH[2], rH[3], sb + AKV + 16384 + off);  // VH
                LDSM_X4_T(rL[0], rL[1], rL[2], rL[3], sb + AKV + 24576 + off);  // VL
                #pragma unroll
                for (int mf = 0; mf < 2; mf++)
                    #pragma unroll
                    for (int s2 = 0; s2 < 2; s2++) {
                        const int nf = 2 * p2 + s2;
                        MMA_F16(o[mf][nf], pH[mf][ks][0], pH[mf][ks][1], pH[mf][ks][2], pH[mf][ks][3], rH[2*s2], rH[2*s2+1]);
                        MMA_F16(o[mf][nf], pH[mf][ks][0], pH[mf][ks][1], pH[mf][ks][2], pH[mf][ks][3], rL[2*s2], rL[2*s2+1]);
                        MMA_F16(o[mf][nf], pL[mf][ks][0], pL[mf][ks][1], pL[mf][ks][2], pL[mf][ks][3], rH[2*s2], rH[2*s2+1]);
                    }
            }
        }
    }

    // ---- finalize: planes carry x256 values -> factor 1/(l*2048) ----
    #pragma unroll
    for (int mf = 0; mf < 2; mf++) {
        const float inv0 = 1.f / (lrow[mf][0] * 2048.f);
        const float inv1 = 1.f / (lrow[mf][1] * 2048.f);
        const int grow0 = qrow0 + w * 32 + mf * 16 + (lane >> 2);
        const int grow1 = grow0 + 8;
        #pragma unroll
        for (int nf = 0; nf < 8; nf++) {
            const int dcol = h * HDIM + nf * 8 + 2 * (lane & 3);
            uint32_t lo;
            uint32_t hi = split_pack(o[mf][nf][0] * inv0, o[mf][nf][1] * inv0, lo);
            *(uint32_t*)(ath + (size_t)grow0 * DMODEL + dcol) = hi;
            *(uint32_t*)(atl + (size_t)grow0 * DMODEL + dcol) = lo;
            hi = split_pack(o[mf][nf][2] * inv1, o[mf][nf][3] * inv1, lo);
            *(uint32_t*)(ath + (size_t)grow1 * DMODEL + dcol) = hi;
            *(uint32_t*)(atl + (size_t)grow1 * DMODEL + dcol) = lo;
        }
    }
}

// ---------------------------------------------------------------------------
extern "C" void kernel_launch(void* const* d_in, const int* in_sizes, int n_in,
                              void* d_out, int out_size) {
    const float* x      = (const float*)d_in[0];   // [4096,1024]
    const float* w_qkv  = (const float*)d_in[1];   // [1024,3072]
    const float* w_out  = (const float*)d_in[2];   // [1024,1024]
    float* out = (float*)d_out;                    // [4096,1024]

    __half *qkvh, *qkvl, *xh, *xl, *wqh, *wql, *ath, *atl, *woh, *wol;
    cudaGetSymbolAddress((void**)&qkvh, g_qkvh);
    cudaGetSymbolAddress((void**)&qkvl, g_qkvl);
    cudaGetSymbolAddress((void**)&xh, g_xh);
    cudaGetSymbolAddress((void**)&xl, g_xl);
    cudaGetSymbolAddress((void**)&wqh, g_wqh);
    cudaGetSymbolAddress((void**)&wql, g_wql);
    cudaGetSymbolAddress((void**)&ath, g_ath);
    cudaGetSymbolAddress((void**)&atl, g_atl);
    cudaGetSymbolAddress((void**)&woh, g_woh);
    cudaGetSymbolAddress((void**)&wol, g_wol);

    const int gemm_smem = 65536;
    cudaFuncSetAttribute(gemm_f16x3<true>, cudaFuncAttributeMaxDynamicSharedMemorySize,
                         gemm_smem);
    cudaFuncSetAttribute(gemm_f16x3<false>, cudaFuncAttributeMaxDynamicSharedMemorySize,
                         gemm_smem);
    cudaFuncSetAttribute(attn_f16v3, cudaFuncAttributeMaxDynamicSharedMemorySize,
                         A_SMEM);

    const int NX = SEQ * DMODEL;

    // split x and w_qkv
    split2h<<<NX / 4 / 256, 256>>>(x, xh, xl, NX);
    split2h_t<<<dim3(D3 / 32, DMODEL / 32), dim3(32, 8)>>>(w_qkv, wqh, wql,
                                                           DMODEL, D3);
    // 1) qkv = x @ w_qkv -> x256-scaled fp16 hi/lo planes
    //    acc carries x65536; planes want value x256 -> outscale = 1/256
    gemm_f16x3<true><<<dim3(D3 / 128, SEQ / 128), 256, gemm_smem>>>(
        xh, xl, wqh, wql, nullptr, qkvh, qkvl, SEQ, D3, DMODEL, 1.f / 256.f);

    // 2) sliding-window attention (consumes planes, writes split planes)
    attn_f16v3<<<dim3(4, NCHUNK, NHEAD), 128, A_SMEM>>>(qkvh, qkvl, ath, atl);

    // split w_out
    split2h_t<<<dim3(DMODEL / 32, DMODEL / 32), dim3(32, 8)>>>(w_out, woh, wol,
                                                               DMODEL, DMODEL);
    // 3) out = attn @ w_out (fp32 out, undo 256*256)
    gemm_f16x3<false><<<dim3(DMODEL / 128, SEQ / 128), 256, gemm_smem>>>(
        ath, atl, woh, wol, out, nullptr, nullptr, SEQ, DMODEL, DMODEL,
        1.f / 65536.f);
}

// round 10
// speedup vs baseline: 2.0043x; 1.0630x over previous
#include <cuda_runtime.h>
#include <cuda_fp16.h>
#include <cstdint>

// Problem constants
#define SEQ    4096
#define DMODEL 1024
#define D3     3072
#define NHEAD  16
#define HDIM   64
#define WIN    512
#define NCHUNK 8

// Scratch (device globals: allocation-free per harness rules)
__device__ __half g_qkvh[SEQ * D3];           // qkv hi plane (x256)
__device__ __half g_qkvl[SEQ * D3];           // qkv lo plane
__device__ __half g_xh[SEQ * DMODEL];
__device__ __half g_xl[SEQ * DMODEL];
__device__ __half g_wqh[D3 * DMODEL];         // w_qkv^T planes [N][K]
__device__ __half g_wql[D3 * DMODEL];
__device__ __half g_ath[SEQ * DMODEL];        // attn split planes (x256)
__device__ __half g_atl[SEQ * DMODEL];
__device__ __half g_woh[DMODEL * DMODEL];     // w_out^T planes [N][K]
__device__ __half g_wol[DMODEL * DMODEL];

// ---------------------------------------------------------------------------
// helpers
// ---------------------------------------------------------------------------
__device__ __forceinline__ void split_h(float x, __half& hi, __half& lo) {
    hi = __float2half_rn(x);
    lo = __float2half_rn(x - __half2float(hi));
}
__device__ __forceinline__ uint32_t pack_h2(__half a, __half b) {
    __half2 h = __halves2half2(a, b);
    return *reinterpret_cast<uint32_t*>(&h);
}
__device__ __forceinline__ uint32_t split_pack(float x, float y, uint32_t& lo) {
    __half hx, lx, hy, ly;
    split_h(x, hx, lx); split_h(y, hy, ly);
    lo = pack_h2(lx, ly);
    return pack_h2(hx, hy);
}

#define MMA_F16(d, a0, a1, a2, a3, b0, b1)                                     \
    asm volatile(                                                              \
        "mma.sync.aligned.m16n8k16.row.col.f32.f16.f16.f32 "                   \
        "{%0,%1,%2,%3}, {%4,%5,%6,%7}, {%8,%9}, {%0,%1,%2,%3};"                \
        : "+f"((d)[0]), "+f"((d)[1]), "+f"((d)[2]), "+f"((d)[3])               \
        : "r"(a0), "r"(a1), "r"(a2), "r"(a3), "r"(b0), "r"(b1))

#define LDSM_X4(r0, r1, r2, r3, addr)                                          \
    asm volatile("ldmatrix.sync.aligned.m8n8.x4.shared.b16 {%0,%1,%2,%3}, [%4];" \
        : "=r"(r0), "=r"(r1), "=r"(r2), "=r"(r3) : "r"(addr))

#define LDSM_X4_T(r0, r1, r2, r3, addr)                                        \
    asm volatile("ldmatrix.sync.aligned.m8n8.x4.trans.shared.b16 {%0,%1,%2,%3}, [%4];" \
        : "=r"(r0), "=r"(r1), "=r"(r2), "=r"(r3) : "r"(addr))

#define CP_ASYNC16(dst, src)                                                   \
    asm volatile("cp.async.cg.shared.global [%0], [%1], 16;"                   \
        :: "r"(dst), "l"(src))
#define CP_COMMIT()  asm volatile("cp.async.commit_group;" ::: "memory")
#define CP_WAIT0()   asm volatile("cp.async.wait_group 0;" ::: "memory")

// ---------------------------------------------------------------------------
// Split kernels
// ---------------------------------------------------------------------------
__global__ __launch_bounds__(256) void split2h(const float* __restrict__ in,
                                               __half* __restrict__ hp,
                                               __half* __restrict__ lp, int n) {
    const int idx = (blockIdx.x * 256 + threadIdx.x) * 4;
    if (idx >= n) return;
    const float4 v = *(const float4*)(in + idx);
    uint32_t l0, l1;
    const uint32_t h0 = split_pack(v.x * 256.f, v.y * 256.f, l0);
    const uint32_t h1 = split_pack(v.z * 256.f, v.w * 256.f, l1);
    *(uint2*)(hp + idx) = make_uint2(h0, h1);
    *(uint2*)(lp + idx) = make_uint2(l0, l1);
}

__global__ void split2h_t(const float* __restrict__ w,
                          __half* __restrict__ th, __half* __restrict__ tl,
                          int Kd, int Nd) {
    __shared__ float tile[32][33];
    const int k0 = blockIdx.y * 32, n0 = blockIdx.x * 32;
    const int tx = threadIdx.x, ty = threadIdx.y;
    for (int r = ty; r < 32; r += 8)
        tile[r][tx] = w[(size_t)(k0 + r) * Nd + n0 + tx];
    __syncthreads();
    for (int r = ty; r < 32; r += 8) {
        __half h, l;
        split_h(tile[tx][r] * 256.f, h, l);
        const size_t o = (size_t)(n0 + r) * Kd + k0 + tx;
        th[o] = h; tl[o] = l;
    }
}

// ---------------------------------------------------------------------------
// 3xFP16 GEMM (m16n8k16), cp.async double-buffered: BK=32 per stage, stages
// interleaved in the chunk dimension of 128B rows (stage st = chunks 4st..).
// smem 64 KB, 256 threads, 2 CTAs/SM.
// ---------------------------------------------------------------------------
template <bool SPLIT_OUT>
__global__ __launch_bounds__(256, 2) void gemm_f16x3(
    const __half* __restrict__ Ahg, const __half* __restrict__ Alg,
    const __half* __restrict__ Bhg, const __half* __restrict__ Blg,
    float* __restrict__ Cf, __half* __restrict__ Ch, __half* __restrict__ Cl,
    int M, int N, int K, float outscale) {
    extern __shared__ char smc[];

    const int tid  = threadIdx.x;
    const int lane = tid & 31;
    const int warp = tid >> 5;
    const int warp_m = warp >> 2;
    const int warp_n = warp & 3;

    const int m0 = blockIdx.y * 128;
    const int n0 = blockIdx.x * 128;

    const int lm_row  = (lane & 7) + ((lane >> 3) & 1) * 8;
    const int lm_csel = lane >> 4;
    const int bq = lane >> 2;
    const int bi = lane & 3;

    float acc[4][4][4] = {};

    const uint32_t sb = (uint32_t)__cvta_generic_to_shared(smc);
    const uint32_t* SM32 = (const uint32_t*)smc;

    const __half* base0 = Ahg + (size_t)m0 * K;
    const __half* base1 = Alg + (size_t)m0 * K;
    const __half* base2 = Bhg + (size_t)n0 * K;
    const __half* base3 = Blg + (size_t)n0 * K;

    const int NIT = K >> 5;

    // issue loads for stage (it&1) of k-iteration it
    auto issue = [&](int it) {
        const int k0 = it << 5;
        const int st4 = (it & 1) << 2;
        #pragma unroll
        for (int i = 0; i < 8; i++) {
            const int lin = tid + i * 256;     // 0..2047
            const int pl  = lin >> 9;          // 0:Ah 1:Al 2:Bh 3:Bl
            const int rem = lin & 511;
            const int row = rem >> 2;
            const int ch  = rem & 3;
            const __half* src =
                (pl == 0 ? base0 : pl == 1 ? base1 : pl == 2 ? base2 : base3)
                + (size_t)row * K + k0 + ch * 8;
            const uint32_t dst = sb + pl * 16384 + row * 128 +
                                 (((st4 + ch) ^ (row & 7)) << 4);
            CP_ASYNC16(dst, src);
        }
        CP_COMMIT();
    };

    issue(0);
    for (int it = 0; it < NIT; it++) {
        CP_WAIT0();
        __syncthreads();
        if (it + 1 < NIT) issue(it + 1);

        const int st4 = (it & 1) << 2;
        #pragma unroll
        for (int s = 0; s < 2; s++) {
            const int c0 = st4 + 2 * s;
            uint32_t aH[4][4], aL[4][4];
            #pragma unroll
            for (int mf = 0; mf < 4; mf++) {
                const int m = warp_m * 64 + mf * 16 + lm_row;
                const uint32_t off =
                    (uint32_t)(m * 128 + (((c0 + lm_csel) ^ (m & 7)) << 4));
                LDSM_X4(aH[mf][0], aH[mf][1], aH[mf][2], aH[mf][3], sb + off);
                LDSM_X4(aL[mf][0], aL[mf][1], aL[mf][2], aL[mf][3], sb + 16384 + off);
            }
            #pragma unroll
            for (int nf = 0; nf < 4; nf++) {
                const int n = warp_n * 32 + nf * 8 + bq;
                const int i0 = n * 32 + ((c0 ^ (n & 7)) << 2) + bi;
                const int i1 = n * 32 + (((c0 + 1) ^ (n & 7)) << 2) + bi;
                const uint32_t bh0 = SM32[8192 + i0], bh1 = SM32[8192 + i1];
                const uint32_t bl0 = SM32[12288 + i0], bl1 = SM32[12288 + i1];
                #pragma unroll
                for (int mf = 0; mf < 4; mf++) {
                    MMA_F16(acc[mf][nf], aH[mf][0], aH[mf][1], aH[mf][2], aH[mf][3], bh0, bh1);
                    MMA_F16(acc[mf][nf], aH[mf][0], aH[mf][1], aH[mf][2], aH[mf][3], bl0, bl1);
                    MMA_F16(acc[mf][nf], aL[mf][0], aL[mf][1], aL[mf][2], aL[mf][3], bh0, bh1);
                }
            }
        }
        __syncthreads();
    }

    const int row_in = lane >> 2;
    const int col_in = 2 * (lane & 3);
    #pragma unroll
    for (int mf = 0; mf < 4; mf++) {
        const int gr = m0 + warp_m * 64 + mf * 16 + row_in;
        #pragma unroll
        for (int nf = 0; nf < 4; nf++) {
            const int gc = n0 + warp_n * 32 + nf * 8 + col_in;
            if (SPLIT_OUT) {
                uint32_t lo;
                uint32_t hi = split_pack(acc[mf][nf][0] * outscale,
                                         acc[mf][nf][1] * outscale, lo);
                *(uint32_t*)(Ch + (size_t)gr * N + gc) = hi;
                *(uint32_t*)(Cl + (size_t)gr * N + gc) = lo;
                hi = split_pack(acc[mf][nf][2] * outscale,
                                acc[mf][nf][3] * outscale, lo);
                *(uint32_t*)(Ch + (size_t)(gr + 8) * N + gc) = hi;
                *(uint32_t*)(Cl + (size_t)(gr + 8) * N + gc) = lo;
            } else {
                *(float2*)(Cf + (size_t)gr * N + gc) =
                    make_float2(acc[mf][nf][0] * outscale, acc[mf][nf][1] * outscale);
                *(float2*)(Cf + (size_t)(gr + 8) * N + gc) =
                    make_float2(acc[mf][nf][2] * outscale, acc[mf][nf][3] * outscale);
            }
        }
    }
}

// ---------------------------------------------------------------------------
// Attention v4: R9 structure + cp.async double-buffered K/V.
// smem: QH 0 (16K), QL 16K, then 2 KV buffers of 32K each:
//   buf b at 32768 + b*32768: KH +0, KL +8K, VH +16K, VL +24K.  Total 96 KB.
// ---------------------------------------------------------------------------
#define AQH 0
#define AQL 16384
#define AKV 32768
#define A_SMEM (32768 + 2 * 32768)

__global__ __launch_bounds__(128, 2) void attn_f16v4(
    const __half* __restrict__ qkvh, const __half* __restrict__ qkvl,
    __half* __restrict__ ath, __half* __restrict__ atl) {
    extern __shared__ char smc[];

    const int qt = blockIdx.x;     // 0..3 (128-q tile)
    const int c  = blockIdx.y;     // 0..7
    const int h  = blockIdx.z;     // 0..15
    const int tid  = threadIdx.x;
    const int lane = tid & 31;
    const int w    = tid >> 5;

    const int q0 = qt * 128;
    const int qrow0 = c * WIN + q0;

    const int lm_row  = (lane & 7) + ((lane >> 3) & 1) * 8;
    const int lm_csel = lane >> 4;
    const int gs = (lane >> 4) & 1;
    const int gc2 = (lane >> 3) & 1;
    const uint32_t sb = (uint32_t)__cvta_generic_to_shared(smc);

    const int kb_start = (c == 0) ? (WIN / 64) : 0;
    const int kb_end = ((q0 + 127 + WIN) >> 6) + 1;

    // issue K/V loads for block kb into buffer buf
    auto issue_kv = [&](int kb, int buf) {
        const int jbase = c * WIN + kb * 64 - WIN;
        #pragma unroll
        for (int i = 0; i < 16; i++) {
            const int lin = tid + i * 128;    // 0..2047
            const int pl  = lin >> 9;         // 0:KH 1:KL 2:VH 3:VL
            const int rem = lin & 511;
            const int row = rem >> 3;
            const int ch  = rem & 7;
            const __half* src = ((pl & 1) ? qkvl : qkvh)
                + (size_t)(jbase + row) * D3 + ((pl >> 1) ? 2 * DMODEL : DMODEL)
                + h * HDIM + ch * 8;
            const uint32_t dst = sb + AKV + buf * 32768 + pl * 8192 +
                                 row * 128 + ((ch ^ (row & 7)) << 4);
            CP_ASYNC16(dst, src);
        }
        CP_COMMIT();
    };

    // ---- Q tile (128 rows, hi+lo): regular copy ----
    #pragma unroll
    for (int i = 0; i < 16; i++) {
        const int lin = tid + i * 128;
        const int pl  = lin >> 10;
        const int rem = lin & 1023;
        const int row = rem >> 3;
        const int ch  = rem & 7;
        const __half* src = (pl ? qkvl : qkvh)
            + (size_t)(qrow0 + row) * D3 + h * HDIM + ch * 8;
        const uint4 v = *(const uint4*)src;
        *(uint4*)(smc + pl * 16384 + row * 128 + ((ch ^ (row & 7)) << 4)) = v;
    }
    issue_kv(kb_start, 0);

    float o[2][8][4] = {};
    float mrow[2][2] = {{-1e30f, -1e30f}, {-1e30f, -1e30f}};
    float lrow[2][2] = {{0.f, 0.f}, {0.f, 0.f}};

    int buf = 0;
    for (int kb = kb_start; kb < kb_end; kb++) {
        const int j0 = kb * 64;
        CP_WAIT0();
        __syncthreads();   // KV buf ready; Q visible (iter 1); prev compute done
        if (kb + 1 < kb_end) issue_kv(kb + 1, buf ^ 1);

        const uint32_t kv = sb + AKV + buf * 32768;

        // ---- S = Q K^T : 32q x 64j per warp ----
        float s[2][8][4] = {};
        #pragma unroll
        for (int ks = 0; ks < 4; ks++) {
            uint32_t qf[2][2][4];
            #pragma unroll
            for (int mf = 0; mf < 2; mf++) {
                const int qr = w * 32 + mf * 16 + lm_row;
                const uint32_t off =
                    (uint32_t)(qr * 128 + (((2 * ks + lm_csel) ^ (qr & 7)) << 4));
                LDSM_X4(qf[mf][0][0], qf[mf][0][1], qf[mf][0][2], qf[mf][0][3], sb + AQH + off);
                LDSM_X4(qf[mf][1][0], qf[mf][1][1], qf[mf][1][2], qf[mf][1][3], sb + AQL + off);
            }
            #pragma unroll
            for (int p = 0; p < 4; p++) {
                const int jr = 8 * (2 * p + gs) + (lane & 7);
                const uint32_t off =
                    (uint32_t)(jr * 128 + (((2 * ks + gc2) ^ (jr & 7)) << 4));
                uint32_t rH[4], rL[4];
                LDSM_X4(rH[0], rH[1], rH[2], rH[3], kv + off);
                LDSM_X4(rL[0], rL[1], rL[2], rL[3], kv + 8192 + off);
                #pragma unroll
                for (int mf = 0; mf < 2; mf++)
                    #pragma unroll
                    for (int s2 = 0; s2 < 2; s2++) {
                        const int nf = 2 * p + s2;
                        MMA_F16(s[mf][nf], qf[mf][0][0], qf[mf][0][1], qf[mf][0][2], qf[mf][0][3], rH[2*s2], rH[2*s2+1]);
                        MMA_F16(s[mf][nf], qf[mf][0][0], qf[mf][0][1], qf[mf][0][2], qf[mf][0][3], rL[2*s2], rL[2*s2+1]);
                        MMA_F16(s[mf][nf], qf[mf][1][0], qf[mf][1][1], qf[mf][1][2], qf[mf][1][3], rH[2*s2], rH[2*s2+1]);
                    }
            }
        }

        // ---- mask + register softmax + P frags ----
        uint32_t pH[2][4][4], pL[2][4][4];
        #pragma unroll
        for (int mf = 0; mf < 2; mf++) {
            const int rq0 = q0 + w * 32 + mf * 16 + (lane >> 2);
            const int rq1 = rq0 + 8;
            const float sc = 0.125f / 65536.f;
            #pragma unroll
            for (int nf = 0; nf < 8; nf++) {
                const int col = j0 + nf * 8 + 2 * (lane & 3);
                s[mf][nf][0] = (rq0 + WIN >= col)     ? s[mf][nf][0] * sc : -1e30f;
                s[mf][nf][1] = (rq0 + WIN >= col + 1) ? s[mf][nf][1] * sc : -1e30f;
                s[mf][nf][2] = (rq1 + WIN >= col)     ? s[mf][nf][2] * sc : -1e30f;
                s[mf][nf][3] = (rq1 + WIN >= col + 1) ? s[mf][nf][3] * sc : -1e30f;
            }
            float mx0 = -1e30f, mx1 = -1e30f;
            #pragma unroll
            for (int nf = 0; nf < 8; nf++) {
                mx0 = fmaxf(mx0, fmaxf(s[mf][nf][0], s[mf][nf][1]));
                mx1 = fmaxf(mx1, fmaxf(s[mf][nf][2], s[mf][nf][3]));
            }
            mx0 = fmaxf(mx0, __shfl_xor_sync(0xffffffffu, mx0, 1));
            mx0 = fmaxf(mx0, __shfl_xor_sync(0xffffffffu, mx0, 2));
            mx1 = fmaxf(mx1, __shfl_xor_sync(0xffffffffu, mx1, 1));
            mx1 = fmaxf(mx1, __shfl_xor_sync(0xffffffffu, mx1, 2));
            const float m0n = fmaxf(mrow[mf][0], mx0);
            const float m1n = fmaxf(mrow[mf][1], mx1);
            const float a0 = __expf(mrow[mf][0] - m0n);
            const float a1 = __expf(mrow[mf][1] - m1n);
            float sum0 = 0.f, sum1 = 0.f;
            #pragma unroll
            for (int nf = 0; nf < 8; nf++) {
                s[mf][nf][0] = __expf(s[mf][nf][0] - m0n);
                s[mf][nf][1] = __expf(s[mf][nf][1] - m0n);
                s[mf][nf][2] = __expf(s[mf][nf][2] - m1n);
                s[mf][nf][3] = __expf(s[mf][nf][3] - m1n);
                sum0 += s[mf][nf][0] + s[mf][nf][1];
                sum1 += s[mf][nf][2] + s[mf][nf][3];
            }
            sum0 += __shfl_xor_sync(0xffffffffu, sum0, 1);
            sum0 += __shfl_xor_sync(0xffffffffu, sum0, 2);
            sum1 += __shfl_xor_sync(0xffffffffu, sum1, 1);
            sum1 += __shfl_xor_sync(0xffffffffu, sum1, 2);
            mrow[mf][0] = m0n; mrow[mf][1] = m1n;
            lrow[mf][0] = lrow[mf][0] * a0 + sum0;
            lrow[mf][1] = lrow[mf][1] * a1 + sum1;
            #pragma unroll
            for (int nf = 0; nf < 8; nf++) {
                o[mf][nf][0] *= a0; o[mf][nf][1] *= a0;
                o[mf][nf][2] *= a1; o[mf][nf][3] *= a1;
            }
            #pragma unroll
            for (int ks = 0; ks < 4; ks++) {
                pH[mf][ks][0] = split_pack(s[mf][2*ks][0]   * 2048.f, s[mf][2*ks][1]   * 2048.f, pL[mf][ks][0]);
                pH[mf][ks][1] = split_pack(s[mf][2*ks][2]   * 2048.f, s[mf][2*ks][3]   * 2048.f, pL[mf][ks][1]);
                pH[mf][ks][2] = split_pack(s[mf][2*ks+1][0] * 2048.f, s[mf][2*ks+1][1] * 2048.f, pL[mf][ks][2]);
                pH[mf][ks][3] = split_pack(s[mf][2*ks+1][2] * 2048.f, s[mf][2*ks+1][3] * 2048.f, pL[mf][ks][3]);
            }
        }

        // ---- O += P V : V frags shared across both mf ----
        #pragma unroll
        for (int ks = 0; ks < 4; ks++) {
            #pragma unroll
            for (int p2 = 0; p2 < 4; p2++) {
                const int jr = 16 * ks + 8 * gc2 + (lane & 7);
                const int ch = 2 * p2 + gs;
                const uint32_t off =
                    (uint32_t)(jr * 128 + ((ch ^ (jr & 7)) << 4));
                uint32_t rH[4], rL[4];
                LDSM_X4_T(rH[0], rH[1], rH[2], rH[3], kv + 16384 + off);
                LDSM_X4_T(rL[0], rL[1], rL[2], rL[3], kv + 24576 + off);
                #pragma unroll
                for (int mf = 0; mf < 2; mf++)
                    #pragma unroll
                    for (int s2 = 0; s2 < 2; s2++) {
                        const int nf = 2 * p2 + s2;
                        MMA_F16(o[mf][nf], pH[mf][ks][0], pH[mf][ks][1], pH[mf][ks][2], pH[mf][ks][3], rH[2*s2], rH[2*s2+1]);
                        MMA_F16(o[mf][nf], pH[mf][ks][0], pH[mf][ks][1], pH[mf][ks][2], pH[mf][ks][3], rL[2*s2], rL[2*s2+1]);
                        MMA_F16(o[mf][nf], pL[mf][ks][0], pL[mf][ks][1], pL[mf][ks][2], pL[mf][ks][3], rH[2*s2], rH[2*s2+1]);
                    }
            }
        }
        buf ^= 1;
    }

    // ---- finalize ----
    #pragma unroll
    for (int mf = 0; mf < 2; mf++) {
        const float inv0 = 1.f / (lrow[mf][0] * 2048.f);
        const float inv1 = 1.f / (lrow[mf][1] * 2048.f);
        const int grow0 = qrow0 + w * 32 + mf * 16 + (lane >> 2);
        const int grow1 = grow0 + 8;
        #pragma unroll
        for (int nf = 0; nf < 8; nf++) {
            const int dcol = h * HDIM + nf * 8 + 2 * (lane & 3);
            uint32_t lo;
            uint32_t hi = split_pack(o[mf][nf][0] * inv0, o[mf][nf][1] * inv0, lo);
            *(uint32_t*)(ath + (size_t)grow0 * DMODEL + dcol) = hi;
            *(uint32_t*)(atl + (size_t)grow0 * DMODEL + dcol) = lo;
            hi = split_pack(o[mf][nf][2] * inv1, o[mf][nf][3] * inv1, lo);
            *(uint32_t*)(ath + (size_t)grow1 * DMODEL + dcol) = hi;
            *(uint32_t*)(atl + (size_t)grow1 * DMODEL + dcol) = lo;
        }
    }
}

// ---------------------------------------------------------------------------
extern "C" void kernel_launch(void* const* d_in, const int* in_sizes, int n_in,
                              void* d_out, int out_size) {
    const float* x      = (const float*)d_in[0];
    const float* w_qkv  = (const float*)d_in[1];
    const float* w_out  = (const float*)d_in[2];
    float* out = (float*)d_out;

    __half *qkvh, *qkvl, *xh, *xl, *wqh, *wql, *ath, *atl, *woh, *wol;
    cudaGetSymbolAddress((void**)&qkvh, g_qkvh);
    cudaGetSymbolAddress((void**)&qkvl, g_qkvl);
    cudaGetSymbolAddress((void**)&xh, g_xh);
    cudaGetSymbolAddress((void**)&xl, g_xl);
    cudaGetSymbolAddress((void**)&wqh, g_wqh);
    cudaGetSymbolAddress((void**)&wql, g_wql);
    cudaGetSymbolAddress((void**)&ath, g_ath);
    cudaGetSymbolAddress((void**)&atl, g_atl);
    cudaGetSymbolAddress((void**)&woh, g_woh);
    cudaGetSymbolAddress((void**)&wol, g_wol);

    const int gemm_smem = 65536;
    cudaFuncSetAttribute(gemm_f16x3<true>, cudaFuncAttributeMaxDynamicSharedMemorySize,
                         gemm_smem);
    cudaFuncSetAttribute(gemm_f16x3<false>, cudaFuncAttributeMaxDynamicSharedMemorySize,
                         gemm_smem);
    cudaFuncSetAttribute(attn_f16v4, cudaFuncAttributeMaxDynamicSharedMemorySize,
                         A_SMEM);

    const int NX = SEQ * DMODEL;

    split2h<<<NX / 4 / 256, 256>>>(x, xh, xl, NX);
    split2h_t<<<dim3(D3 / 32, DMODEL / 32), dim3(32, 8)>>>(w_qkv, wqh, wql,
                                                           DMODEL, D3);
    // 1) qkv = x @ w_qkv -> x256-scaled fp16 hi/lo planes
    gemm_f16x3<true><<<dim3(D3 / 128, SEQ / 128), 256, gemm_smem>>>(
        xh, xl, wqh, wql, nullptr, qkvh, qkvl, SEQ, D3, DMODEL, 1.f / 256.f);

    // 2) sliding-window attention
    attn_f16v4<<<dim3(4, NCHUNK, NHEAD), 128, A_SMEM>>>(qkvh, qkvl, ath, atl);

    split2h_t<<<dim3(DMODEL / 32, DMODEL / 32), dim3(32, 8)>>>(w_out, woh, wol,
                                                               DMODEL, DMODEL);
    // 3) out = attn @ w_out (fp32 out)
    gemm_f16x3<false><<<dim3(DMODEL / 128, SEQ / 128), 256, gemm_smem>>>(
        ath, atl, woh, wol, out, nullptr, nullptr, SEQ, DMODEL, DMODEL,
        1.f / 65536.f);
}

// round 11
// speedup vs baseline: 2.0206x; 1.0081x over previous
#include <cuda_runtime.h>
#include <cuda_fp16.h>
#include <cstdint>

// Problem constants
#define SEQ    4096
#define DMODEL 1024
#define D3     3072
#define NHEAD  16
#define HDIM   64
#define WIN    512
#define NCHUNK 8

// Scratch (device globals: allocation-free per harness rules)
__device__ __half g_qkvh[SEQ * D3];           // qkv hi plane (x256)
__device__ __half g_qkvl[SEQ * D3];           // qkv lo plane
__device__ __half g_xh[SEQ * DMODEL];
__device__ __half g_xl[SEQ * DMODEL];
__device__ __half g_wqh[D3 * DMODEL];         // w_qkv^T planes [N][K]
__device__ __half g_wql[D3 * DMODEL];
__device__ __half g_ath[SEQ * DMODEL];        // attn split planes (x256)
__device__ __half g_atl[SEQ * DMODEL];
__device__ __half g_woh[DMODEL * DMODEL];     // w_out^T planes [N][K]
__device__ __half g_wol[DMODEL * DMODEL];

// ---------------------------------------------------------------------------
// helpers
// ---------------------------------------------------------------------------
__device__ __forceinline__ void split_h(float x, __half& hi, __half& lo) {
    hi = __float2half_rn(x);
    lo = __float2half_rn(x - __half2float(hi));
}
// vectorized Dekker split of a float pair -> packed fp16 hi (ret) / lo (out)
__device__ __forceinline__ uint32_t split_pack(float x, float y, uint32_t& lo) {
    __half2 h2 = __float22half2_rn(make_float2(x, y));
    float2 hf = __half22float2(h2);
    __half2 l2 = __float22half2_rn(make_float2(x - hf.x, y - hf.y));
    lo = *reinterpret_cast<uint32_t*>(&l2);
    return *reinterpret_cast<uint32_t*>(&h2);
}
__device__ __forceinline__ float fexp2(float x) {
    float r;
    asm("ex2.approx.f32 %0, %1;" : "=f"(r) : "f"(x));
    return r;
}

#define MMA_F16(d, a0, a1, a2, a3, b0, b1)                                     \
    asm volatile(                                                              \
        "mma.sync.aligned.m16n8k16.row.col.f32.f16.f16.f32 "                   \
        "{%0,%1,%2,%3}, {%4,%5,%6,%7}, {%8,%9}, {%0,%1,%2,%3};"                \
        : "+f"((d)[0]), "+f"((d)[1]), "+f"((d)[2]), "+f"((d)[3])               \
        : "r"(a0), "r"(a1), "r"(a2), "r"(a3), "r"(b0), "r"(b1))

#define LDSM_X4(r0, r1, r2, r3, addr)                                          \
    asm volatile("ldmatrix.sync.aligned.m8n8.x4.shared.b16 {%0,%1,%2,%3}, [%4];" \
        : "=r"(r0), "=r"(r1), "=r"(r2), "=r"(r3) : "r"(addr))

#define LDSM_X4_T(r0, r1, r2, r3, addr)                                        \
    asm volatile("ldmatrix.sync.aligned.m8n8.x4.trans.shared.b16 {%0,%1,%2,%3}, [%4];" \
        : "=r"(r0), "=r"(r1), "=r"(r2), "=r"(r3) : "r"(addr))

#define CP_ASYNC16(dst, src)                                                   \
    asm volatile("cp.async.cg.shared.global [%0], [%1], 16;"                   \
        :: "r"(dst), "l"(src))
#define CP_COMMIT()  asm volatile("cp.async.commit_group;" ::: "memory")
#define CP_WAIT0()   asm volatile("cp.async.wait_group 0;" ::: "memory")

// ---------------------------------------------------------------------------
// Split kernels
// ---------------------------------------------------------------------------
__global__ __launch_bounds__(256) void split2h(const float* __restrict__ in,
                                               __half* __restrict__ hp,
                                               __half* __restrict__ lp, int n) {
    const int idx = (blockIdx.x * 256 + threadIdx.x) * 4;
    if (idx >= n) return;
    const float4 v = *(const float4*)(in + idx);
    uint32_t l0, l1;
    const uint32_t h0 = split_pack(v.x * 256.f, v.y * 256.f, l0);
    const uint32_t h1 = split_pack(v.z * 256.f, v.w * 256.f, l1);
    *(uint2*)(hp + idx) = make_uint2(h0, h1);
    *(uint2*)(lp + idx) = make_uint2(l0, l1);
}

__global__ void split2h_t(const float* __restrict__ w,
                          __half* __restrict__ th, __half* __restrict__ tl,
                          int Kd, int Nd) {
    __shared__ float tile[32][33];
    const int k0 = blockIdx.y * 32, n0 = blockIdx.x * 32;
    const int tx = threadIdx.x, ty = threadIdx.y;
    for (int r = ty; r < 32; r += 8)
        tile[r][tx] = w[(size_t)(k0 + r) * Nd + n0 + tx];
    __syncthreads();
    for (int r = ty; r < 32; r += 8) {
        __half h, l;
        split_h(tile[tx][r] * 256.f, h, l);
        const size_t o = (size_t)(n0 + r) * Kd + k0 + tx;
        th[o] = h; tl[o] = l;
    }
}

// ---------------------------------------------------------------------------
// 3xFP16 GEMM (m16n8k16), cp.async double-buffered (unchanged from R10).
// ---------------------------------------------------------------------------
template <bool SPLIT_OUT>
__global__ __launch_bounds__(256, 2) void gemm_f16x3(
    const __half* __restrict__ Ahg, const __half* __restrict__ Alg,
    const __half* __restrict__ Bhg, const __half* __restrict__ Blg,
    float* __restrict__ Cf, __half* __restrict__ Ch, __half* __restrict__ Cl,
    int M, int N, int K, float outscale) {
    extern __shared__ char smc[];

    const int tid  = threadIdx.x;
    const int lane = tid & 31;
    const int warp = tid >> 5;
    const int warp_m = warp >> 2;
    const int warp_n = warp & 3;

    const int m0 = blockIdx.y * 128;
    const int n0 = blockIdx.x * 128;

    const int lm_row  = (lane & 7) + ((lane >> 3) & 1) * 8;
    const int lm_csel = lane >> 4;
    const int bq = lane >> 2;
    const int bi = lane & 3;

    float acc[4][4][4] = {};

    const uint32_t sb = (uint32_t)__cvta_generic_to_shared(smc);
    const uint32_t* SM32 = (const uint32_t*)smc;

    const __half* base0 = Ahg + (size_t)m0 * K;
    const __half* base1 = Alg + (size_t)m0 * K;
    const __half* base2 = Bhg + (size_t)n0 * K;
    const __half* base3 = Blg + (size_t)n0 * K;

    const int NIT = K >> 5;

    auto issue = [&](int it) {
        const int k0 = it << 5;
        const int st4 = (it & 1) << 2;
        #pragma unroll
        for (int i = 0; i < 8; i++) {
            const int lin = tid + i * 256;
            const int pl  = lin >> 9;
            const int rem = lin & 511;
            const int row = rem >> 2;
            const int ch  = rem & 3;
            const __half* src =
                (pl == 0 ? base0 : pl == 1 ? base1 : pl == 2 ? base2 : base3)
                + (size_t)row * K + k0 + ch * 8;
            const uint32_t dst = sb + pl * 16384 + row * 128 +
                                 (((st4 + ch) ^ (row & 7)) << 4);
            CP_ASYNC16(dst, src);
        }
        CP_COMMIT();
    };

    issue(0);
    for (int it = 0; it < NIT; it++) {
        CP_WAIT0();
        __syncthreads();
        if (it + 1 < NIT) issue(it + 1);

        const int st4 = (it & 1) << 2;
        #pragma unroll
        for (int s = 0; s < 2; s++) {
            const int c0 = st4 + 2 * s;
            uint32_t aH[4][4], aL[4][4];
            #pragma unroll
            for (int mf = 0; mf < 4; mf++) {
                const int m = warp_m * 64 + mf * 16 + lm_row;
                const uint32_t off =
                    (uint32_t)(m * 128 + (((c0 + lm_csel) ^ (m & 7)) << 4));
                LDSM_X4(aH[mf][0], aH[mf][1], aH[mf][2], aH[mf][3], sb + off);
                LDSM_X4(aL[mf][0], aL[mf][1], aL[mf][2], aL[mf][3], sb + 16384 + off);
            }
            #pragma unroll
            for (int nf = 0; nf < 4; nf++) {
                const int n = warp_n * 32 + nf * 8 + bq;
                const int i0 = n * 32 + ((c0 ^ (n & 7)) << 2) + bi;
                const int i1 = n * 32 + (((c0 + 1) ^ (n & 7)) << 2) + bi;
                const uint32_t bh0 = SM32[8192 + i0], bh1 = SM32[8192 + i1];
                const uint32_t bl0 = SM32[12288 + i0], bl1 = SM32[12288 + i1];
                #pragma unroll
                for (int mf = 0; mf < 4; mf++) {
                    MMA_F16(acc[mf][nf], aH[mf][0], aH[mf][1], aH[mf][2], aH[mf][3], bh0, bh1);
                    MMA_F16(acc[mf][nf], aH[mf][0], aH[mf][1], aH[mf][2], aH[mf][3], bl0, bl1);
                    MMA_F16(acc[mf][nf], aL[mf][0], aL[mf][1], aL[mf][2], aL[mf][3], bh0, bh1);
                }
            }
        }
        __syncthreads();
    }

    const int row_in = lane >> 2;
    const int col_in = 2 * (lane & 3);
    #pragma unroll
    for (int mf = 0; mf < 4; mf++) {
        const int gr = m0 + warp_m * 64 + mf * 16 + row_in;
        #pragma unroll
        for (int nf = 0; nf < 4; nf++) {
            const int gc = n0 + warp_n * 32 + nf * 8 + col_in;
            if (SPLIT_OUT) {
                uint32_t lo;
                uint32_t hi = split_pack(acc[mf][nf][0] * outscale,
                                         acc[mf][nf][1] * outscale, lo);
                *(uint32_t*)(Ch + (size_t)gr * N + gc) = hi;
                *(uint32_t*)(Cl + (size_t)gr * N + gc) = lo;
                hi = split_pack(acc[mf][nf][2] * outscale,
                                acc[mf][nf][3] * outscale, lo);
                *(uint32_t*)(Ch + (size_t)(gr + 8) * N + gc) = hi;
                *(uint32_t*)(Cl + (size_t)(gr + 8) * N + gc) = lo;
            } else {
                *(float2*)(Cf + (size_t)gr * N + gc) =
                    make_float2(acc[mf][nf][0] * outscale, acc[mf][nf][1] * outscale);
                *(float2*)(Cf + (size_t)(gr + 8) * N + gc) =
                    make_float2(acc[mf][nf][2] * outscale, acc[mf][nf][3] * outscale);
            }
        }
    }
}

// ---------------------------------------------------------------------------
// Attention v5: R10 + raw-domain exp2 softmax, diagonal-only masking,
// per-warp fully-masked-block skip, vectorized P split.
// Raw S units: s_mma = 65536 * 8 * S_true; C = 0.125/65536*log2(e).
// p2048 = ex2(s*C - (m*C - 11)); l accumulates p2048; out factor 1/l'.
// ---------------------------------------------------------------------------
#define AQH 0
#define AQL 16384
#define AKV 32768
#define A_SMEM (32768 + 2 * 32768)
#define EXP_C (0.125f / 65536.f * 1.4426950408889634f)

__global__ __launch_bounds__(128, 2) void attn_f16v5(
    const __half* __restrict__ qkvh, const __half* __restrict__ qkvl,
    __half* __restrict__ ath, __half* __restrict__ atl) {
    extern __shared__ char smc[];

    const int qt = blockIdx.x;     // 0..3
    const int c  = blockIdx.y;     // 0..7
    const int h  = blockIdx.z;     // 0..15
    const int tid  = threadIdx.x;
    const int lane = tid & 31;
    const int w    = tid >> 5;

    const int q0 = qt * 128;
    const int qrow0 = c * WIN + q0;

    const int lm_row  = (lane & 7) + ((lane >> 3) & 1) * 8;
    const int lm_csel = lane >> 4;
    const int gs = (lane >> 4) & 1;
    const int gc2 = (lane >> 3) & 1;
    const uint32_t sb = (uint32_t)__cvta_generic_to_shared(smc);

    const int kb_start = (c == 0) ? (WIN / 64) : 0;
    const int kb_end = ((q0 + 127 + WIN) >> 6) + 1;

    auto issue_kv = [&](int kb, int buf) {
        const int jbase = c * WIN + kb * 64 - WIN;
        #pragma unroll
        for (int i = 0; i < 16; i++) {
            const int lin = tid + i * 128;
            const int pl  = lin >> 9;
            const int rem = lin & 511;
            const int row = rem >> 3;
            const int ch  = rem & 7;
            const __half* src = ((pl & 1) ? qkvl : qkvh)
                + (size_t)(jbase + row) * D3 + ((pl >> 1) ? 2 * DMODEL : DMODEL)
                + h * HDIM + ch * 8;
            const uint32_t dst = sb + AKV + buf * 32768 + pl * 8192 +
                                 row * 128 + ((ch ^ (row & 7)) << 4);
            CP_ASYNC16(dst, src);
        }
        CP_COMMIT();
    };

    // Q tile
    #pragma unroll
    for (int i = 0; i < 16; i++) {
        const int lin = tid + i * 128;
        const int pl  = lin >> 10;
        const int rem = lin & 1023;
        const int row = rem >> 3;
        const int ch  = rem & 7;
        const __half* src = (pl ? qkvl : qkvh)
            + (size_t)(qrow0 + row) * D3 + h * HDIM + ch * 8;
        const uint4 v = *(const uint4*)src;
        *(uint4*)(smc + pl * 16384 + row * 128 + ((ch ^ (row & 7)) << 4)) = v;
    }
    issue_kv(kb_start, 0);

    float o[2][8][4] = {};
    float mrow[2][2] = {{-1e30f, -1e30f}, {-1e30f, -1e30f}};
    float lrow[2][2] = {{0.f, 0.f}, {0.f, 0.f}};

    int buf = 0;
    for (int kb = kb_start; kb < kb_end; kb++) {
        const int j0 = kb * 64;
        CP_WAIT0();
        __syncthreads();
        if (kb + 1 < kb_end) issue_kv(kb + 1, buf ^ 1);

        // warp-block fully masked? (smallest key col beyond largest query+WIN)
        if (j0 <= q0 + w * 32 + 31 + WIN) {
            const uint32_t kv = sb + AKV + buf * 32768;

            // ---- S = Q K^T (raw units) ----
            float s[2][8][4] = {};
            #pragma unroll
            for (int ks = 0; ks < 4; ks++) {
                uint32_t qf[2][2][4];
                #pragma unroll
                for (int mf = 0; mf < 2; mf++) {
                    const int qr = w * 32 + mf * 16 + lm_row;
                    const uint32_t off =
                        (uint32_t)(qr * 128 + (((2 * ks + lm_csel) ^ (qr & 7)) << 4));
                    LDSM_X4(qf[mf][0][0], qf[mf][0][1], qf[mf][0][2], qf[mf][0][3], sb + AQH + off);
                    LDSM_X4(qf[mf][1][0], qf[mf][1][1], qf[mf][1][2], qf[mf][1][3], sb + AQL + off);
                }
                #pragma unroll
                for (int p = 0; p < 4; p++) {
                    const int jr = 8 * (2 * p + gs) + (lane & 7);
                    const uint32_t off =
                        (uint32_t)(jr * 128 + (((2 * ks + gc2) ^ (jr & 7)) << 4));
                    uint32_t rH[4], rL[4];
                    LDSM_X4(rH[0], rH[1], rH[2], rH[3], kv + off);
                    LDSM_X4(rL[0], rL[1], rL[2], rL[3], kv + 8192 + off);
                    #pragma unroll
                    for (int mf = 0; mf < 2; mf++)
                        #pragma unroll
                        for (int s2 = 0; s2 < 2; s2++) {
                            const int nf = 2 * p + s2;
                            MMA_F16(s[mf][nf], qf[mf][0][0], qf[mf][0][1], qf[mf][0][2], qf[mf][0][3], rH[2*s2], rH[2*s2+1]);
                            MMA_F16(s[mf][nf], qf[mf][0][0], qf[mf][0][1], qf[mf][0][2], qf[mf][0][3], rL[2*s2], rL[2*s2+1]);
                            MMA_F16(s[mf][nf], qf[mf][1][0], qf[mf][1][1], qf[mf][1][2], qf[mf][1][3], rH[2*s2], rH[2*s2+1]);
                        }
                }
            }

            // mask needed only on diagonal blocks for this warp
            const bool needmask = (j0 + 63 > q0 + w * 32 + WIN);

            uint32_t pH[2][4][4], pL[2][4][4];
            #pragma unroll
            for (int mf = 0; mf < 2; mf++) {
                if (needmask) {
                    const int rq0 = q0 + w * 32 + mf * 16 + (lane >> 2);
                    const int rq1 = rq0 + 8;
                    #pragma unroll
                    for (int nf = 0; nf < 8; nf++) {
                        const int col = j0 + nf * 8 + 2 * (lane & 3);
                        if (rq0 + WIN < col)     s[mf][nf][0] = -3e38f;
                        if (rq0 + WIN < col + 1) s[mf][nf][1] = -3e38f;
                        if (rq1 + WIN < col)     s[mf][nf][2] = -3e38f;
                        if (rq1 + WIN < col + 1) s[mf][nf][3] = -3e38f;
                    }
                }
                float mx0 = -3e38f, mx1 = -3e38f;
                #pragma unroll
                for (int nf = 0; nf < 8; nf++) {
                    mx0 = fmaxf(mx0, fmaxf(s[mf][nf][0], s[mf][nf][1]));
                    mx1 = fmaxf(mx1, fmaxf(s[mf][nf][2], s[mf][nf][3]));
                }
                mx0 = fmaxf(mx0, __shfl_xor_sync(0xffffffffu, mx0, 1));
                mx0 = fmaxf(mx0, __shfl_xor_sync(0xffffffffu, mx0, 2));
                mx1 = fmaxf(mx1, __shfl_xor_sync(0xffffffffu, mx1, 1));
                mx1 = fmaxf(mx1, __shfl_xor_sync(0xffffffffu, mx1, 2));
                const float m0n = fmaxf(mrow[mf][0], mx0);
                const float m1n = fmaxf(mrow[mf][1], mx1);
                const float a0 = fexp2((mrow[mf][0] - m0n) * EXP_C);
                const float a1 = fexp2((mrow[mf][1] - m1n) * EXP_C);
                const float b0 = m0n * EXP_C - 11.f;   // fold x2048
                const float b1 = m1n * EXP_C - 11.f;
                float sum0 = 0.f, sum1 = 0.f;
                #pragma unroll
                for (int nf = 0; nf < 8; nf++) {
                    s[mf][nf][0] = fexp2(fmaf(s[mf][nf][0], EXP_C, -b0));
                    s[mf][nf][1] = fexp2(fmaf(s[mf][nf][1], EXP_C, -b0));
                    s[mf][nf][2] = fexp2(fmaf(s[mf][nf][2], EXP_C, -b1));
                    s[mf][nf][3] = fexp2(fmaf(s[mf][nf][3], EXP_C, -b1));
                    sum0 += s[mf][nf][0] + s[mf][nf][1];
                    sum1 += s[mf][nf][2] + s[mf][nf][3];
                }
                sum0 += __shfl_xor_sync(0xffffffffu, sum0, 1);
                sum0 += __shfl_xor_sync(0xffffffffu, sum0, 2);
                sum1 += __shfl_xor_sync(0xffffffffu, sum1, 1);
                sum1 += __shfl_xor_sync(0xffffffffu, sum1, 2);
                mrow[mf][0] = m0n; mrow[mf][1] = m1n;
                lrow[mf][0] = lrow[mf][0] * a0 + sum0;
                lrow[mf][1] = lrow[mf][1] * a1 + sum1;
                #pragma unroll
                for (int nf = 0; nf < 8; nf++) {
                    o[mf][nf][0] *= a0; o[mf][nf][1] *= a0;
                    o[mf][nf][2] *= a1; o[mf][nf][3] *= a1;
                }
                #pragma unroll
                for (int ks = 0; ks < 4; ks++) {
                    pH[mf][ks][0] = split_pack(s[mf][2*ks][0],   s[mf][2*ks][1],   pL[mf][ks][0]);
                    pH[mf][ks][1] = split_pack(s[mf][2*ks][2],   s[mf][2*ks][3],   pL[mf][ks][1]);
                    pH[mf][ks][2] = split_pack(s[mf][2*ks+1][0], s[mf][2*ks+1][1], pL[mf][ks][2]);
                    pH[mf][ks][3] = split_pack(s[mf][2*ks+1][2], s[mf][2*ks+1][3], pL[mf][ks][3]);
                }
            }

            // ---- O += P V ----
            #pragma unroll
            for (int ks = 0; ks < 4; ks++) {
                #pragma unroll
                for (int p2 = 0; p2 < 4; p2++) {
                    const int jr = 16 * ks + 8 * gc2 + (lane & 7);
                    const int ch = 2 * p2 + gs;
                    const uint32_t off =
                        (uint32_t)(jr * 128 + ((ch ^ (jr & 7)) << 4));
                    uint32_t rH[4], rL[4];
                    LDSM_X4_T(rH[0], rH[1], rH[2], rH[3], kv + 16384 + off);
                    LDSM_X4_T(rL[0], rL[1], rL[2], rL[3], kv + 24576 + off);
                    #pragma unroll
                    for (int mf = 0; mf < 2; mf++)
                        #pragma unroll
                        for (int s2 = 0; s2 < 2; s2++) {
                            const int nf = 2 * p2 + s2;
                            MMA_F16(o[mf][nf], pH[mf][ks][0], pH[mf][ks][1], pH[mf][ks][2], pH[mf][ks][3], rH[2*s2], rH[2*s2+1]);
                            MMA_F16(o[mf][nf], pH[mf][ks][0], pH[mf][ks][1], pH[mf][ks][2], pH[mf][ks][3], rL[2*s2], rL[2*s2+1]);
                            MMA_F16(o[mf][nf], pL[mf][ks][0], pL[mf][ks][1], pL[mf][ks][2], pL[mf][ks][3], rH[2*s2], rH[2*s2+1]);
                        }
                }
            }
        }
        buf ^= 1;
    }

    // ---- finalize: o = sum(p2048 * v256); planes want v*256 -> 1/l' ----
    #pragma unroll
    for (int mf = 0; mf < 2; mf++) {
        const float inv0 = 1.f / lrow[mf][0];
        const float inv1 = 1.f / lrow[mf][1];
        const int grow0 = qrow0 + w * 32 + mf * 16 + (lane >> 2);
        const int grow1 = grow0 + 8;
        #pragma unroll
        for (int nf = 0; nf < 8; nf++) {
            const int dcol = h * HDIM + nf * 8 + 2 * (lane & 3);
            uint32_t lo;
            uint32_t hi = split_pack(o[mf][nf][0] * inv0, o[mf][nf][1] * inv0, lo);
            *(uint32_t*)(ath + (size_t)grow0 * DMODEL + dcol) = hi;
            *(uint32_t*)(atl + (size_t)grow0 * DMODEL + dcol) = lo;
            hi = split_pack(o[mf][nf][2] * inv1, o[mf][nf][3] * inv1, lo);
            *(uint32_t*)(ath + (size_t)grow1 * DMODEL + dcol) = hi;
            *(uint32_t*)(atl + (size_t)grow1 * DMODEL + dcol) = lo;
        }
    }
}

// ---------------------------------------------------------------------------
extern "C" void kernel_launch(void* const* d_in, const int* in_sizes, int n_in,
                              void* d_out, int out_size) {
    const float* x      = (const float*)d_in[0];
    const float* w_qkv  = (const float*)d_in[1];
    const float* w_out  = (const float*)d_in[2];
    float* out = (float*)d_out;

    __half *qkvh, *qkvl, *xh, *xl, *wqh, *wql, *ath, *atl, *woh, *wol;
    cudaGetSymbolAddress((void**)&qkvh, g_qkvh);
    cudaGetSymbolAddress((void**)&qkvl, g_qkvl);
    cudaGetSymbolAddress((void**)&xh, g_xh);
    cudaGetSymbolAddress((void**)&xl, g_xl);
    cudaGetSymbolAddress((void**)&wqh, g_wqh);
    cudaGetSymbolAddress((void**)&wql, g_wql);
    cudaGetSymbolAddress((void**)&ath, g_ath);
    cudaGetSymbolAddress((void**)&atl, g_atl);
    cudaGetSymbolAddress((void**)&woh, g_woh);
    cudaGetSymbolAddress((void**)&wol, g_wol);

    const int gemm_smem = 65536;
    cudaFuncSetAttribute(gemm_f16x3<true>, cudaFuncAttributeMaxDynamicSharedMemorySize,
                         gemm_smem);
    cudaFuncSetAttribute(gemm_f16x3<false>, cudaFuncAttributeMaxDynamicSharedMemorySize,
                         gemm_smem);
    cudaFuncSetAttribute(attn_f16v5, cudaFuncAttributeMaxDynamicSharedMemorySize,
                         A_SMEM);

    const int NX = SEQ * DMODEL;

    split2h<<<NX / 4 / 256, 256>>>(x, xh, xl, NX);
    split2h_t<<<dim3(D3 / 32, DMODEL / 32), dim3(32, 8)>>>(w_qkv, wqh, wql,
                                                           DMODEL, D3);
    gemm_f16x3<true><<<dim3(D3 / 128, SEQ / 128), 256, gemm_smem>>>(
        xh, xl, wqh, wql, nullptr, qkvh, qkvl, SEQ, D3, DMODEL, 1.f / 256.f);

    attn_f16v5<<<dim3(4, NCHUNK, NHEAD), 128, A_SMEM>>>(qkvh, qkvl, ath, atl);

    split2h_t<<<dim3(DMODEL / 32, DMODEL / 32), dim3(32, 8)>>>(w_out, woh, wol,
                                                               DMODEL, DMODEL);
    gemm_f16x3<false><<<dim3(DMODEL / 128, SEQ / 128), 256, gemm_smem>>>(
        ath, atl, woh, wol, out, nullptr, nullptr, SEQ, DMODEL, DMODEL,
        1.f / 65536.f);
}